// round 2
// baseline (speedup 1.0000x reference)
#include <cuda_runtime.h>
#include <cuda_bf16.h>
#include <cstdint>

// ---------------- problem constants ----------------
#define NB  16
#define HN  8
#define HDM 32
#define DM  256
#define GP  512
#define GD  128
#define NHS 128          // NB*HN slices
#define LPT 2048
#define LDT 512
// scale * log2(e) for exp2f-based exp(l/sqrt(32))
#define EXPSC 0.2550526808750678f   // (1/sqrt(32)) * 1.4426950408889634

// ---------------- scratch (static device globals; no runtime alloc) ----------------
__device__ float g_pg[NB*GP*DM];        // grouped protein  [n*GP+g][256]
__device__ float g_dg[NB*GD*DM];        // grouped drug
__device__ float g_mp[NB*GP];           // protein group mask (0/1)
__device__ float g_md[NB*GD];           // drug group mask
__device__ float g_sp[NB*DM];           // masked sum of grouped protein
__device__ float g_sd[NB*DM];           // masked sum of grouped drug
__device__ float g_cnt[2*NB];           // valid-group counts [ent][n]
__device__ float g_kp[NHS*GP*HDM];      // K_protein  [(n*8+h)*512 + j][32]
__device__ float g_qd[NHS*GD*HDM];      // Q_drug     [(n*8+h)*128 + i][32]
__device__ float g_E [NHS*GD*GP];       // E = valid*exp(scaled logits), fp32, [slice][i][j]
__device__ float g_r [NHS*GD];          // row scalings
__device__ float g_cs[NHS*GP];          // column sums (c = 1/cs)
__device__ int   g_maskmode;

// ---------------- mask dtype probe ----------------
__global__ void k_probe(const unsigned int* __restrict__ m) {
    if (threadIdx.x != 0 || blockIdx.x != 0) return;
    int cbf = 0, cf = 0, ch16 = 0, big = 0;
    for (int i = 0; i < 256; i++) {
        unsigned w = m[i];
        cbf  += (w == 0x3F803F80u);
        cf   += (w == 0x3F800000u);
        ch16 += (w == 0x3C003C00u);
        big  += (w > 1u);
    }
    int mode;
    if (cbf >= 4)       mode = 3;   // bf16
    else if (ch16 >= 4) mode = 3;   // fp16 (same 16-bit nonzero decode)
    else if (cf >= 4)   mode = 0;   // f32
    else if (big > 0)   mode = 2;   // u8 / bool bytes
    else                mode = 1;   // i32
    g_maskmode = mode;
}

__device__ __forceinline__ float mask_at(const void* M, int tok, int mode) {
    switch (mode) {
        case 0:  return ((const float*)M)[tok] != 0.0f ? 1.0f : 0.0f;
        case 1:  return ((const int*)M)[tok]   != 0    ? 1.0f : 0.0f;
        case 2:  return ((const unsigned char*)M)[tok] ? 1.0f : 0.0f;
        default: return ((const unsigned short*)M)[tok] ? 1.0f : 0.0f;
    }
}

// ---------------- grouping: mean over GS=4 tokens + any() mask ----------------
__global__ void k_group(const float* __restrict__ X, const void* __restrict__ M,
                        int G, int isDrug) {
    int b = blockIdx.x;          // b = n*G + g
    int d = threadIdx.x;
    const float* src = X + (size_t)b * 4 * DM;
    float v = 0.25f * (src[d] + src[DM + d] + src[2*DM + d] + src[3*DM + d]);
    float* out = isDrug ? g_dg : g_pg;
    out[(size_t)b * DM + d] = v;
    if (d == 0) {
        int mode = g_maskmode;
        float m = mask_at(M, 4*b+0, mode) + mask_at(M, 4*b+1, mode)
                + mask_at(M, 4*b+2, mode) + mask_at(M, 4*b+3, mode);
        (isDrug ? g_md : g_mp)[b] = (m > 0.0f) ? 1.0f : 0.0f;
    }
}

// ---------------- masked sums over groups + counts ----------------
__global__ void k_msum() {
    int n = blockIdx.x, ent = blockIdx.y, d = threadIdx.x;
    const float* X = ent ? g_dg : g_pg;
    const float* m = ent ? g_md : g_mp;
    int G = ent ? GD : GP;
    float acc = 0.0f;
    for (int g = 0; g < G; g++)
        acc += m[n*G + g] * X[((size_t)(n*G + g))*DM + d];
    (ent ? g_sd : g_sp)[n*DM + d] = acc;
    if (d == 0) {
        float c = 0.0f;
        for (int g = 0; g < G; g++) c += m[n*G + g];
        g_cnt[ent*NB + n] = c;
    }
}

// ---------------- projection GEMM: OUT = group(X) @ W^T (head-split layout) ----
// 128x128 tile, K=256 in steps of 16, 256 threads, 8x8 micro-tile.
__global__ __launch_bounds__(256) void k_proj(const float* __restrict__ Wkp,
                                              const float* __restrict__ Wqd) {
    const float* X; const float* W; float* OUT; int L;
    if (blockIdx.z == 0) { X = g_pg; W = Wkp; OUT = g_kp; L = GP; }
    else                 { if (blockIdx.x >= 16) return;
                           X = g_dg; W = Wqd; OUT = g_qd; L = GD; }
    __shared__ float Xs[16][132];
    __shared__ float Ws[16][132];
    int tid = threadIdx.x;
    int tx = tid & 15, ty = tid >> 4;
    int m0 = blockIdx.x * 128, o0 = blockIdx.y * 128;

    float acc[8][8];
#pragma unroll
    for (int u = 0; u < 8; u++)
#pragma unroll
        for (int v = 0; v < 8; v++) acc[u][v] = 0.0f;

    for (int k0 = 0; k0 < 256; k0 += 16) {
#pragma unroll
        for (int s = 0; s < 2; s++) {
            int f = tid + s*256;          // 512 float4 per tile
            int row = f >> 2, c4 = f & 3;
            float4 vx = *(const float4*)&X[(size_t)(m0+row)*256 + k0 + c4*4];
            Xs[c4*4+0][row] = vx.x; Xs[c4*4+1][row] = vx.y;
            Xs[c4*4+2][row] = vx.z; Xs[c4*4+3][row] = vx.w;
            float4 vw = *(const float4*)&W[(size_t)(o0+row)*256 + k0 + c4*4];
            Ws[c4*4+0][row] = vw.x; Ws[c4*4+1][row] = vw.y;
            Ws[c4*4+2][row] = vw.z; Ws[c4*4+3][row] = vw.w;
        }
        __syncthreads();
#pragma unroll
        for (int kk = 0; kk < 16; kk++) {
            float4 a0 = *(const float4*)&Xs[kk][ty*8];
            float4 a1 = *(const float4*)&Xs[kk][ty*8+4];
            float4 b0 = *(const float4*)&Ws[kk][tx*8];
            float4 b1 = *(const float4*)&Ws[kk][tx*8+4];
            float a[8] = {a0.x,a0.y,a0.z,a0.w,a1.x,a1.y,a1.z,a1.w};
            float b[8] = {b0.x,b0.y,b0.z,b0.w,b1.x,b1.y,b1.z,b1.w};
#pragma unroll
            for (int u = 0; u < 8; u++)
#pragma unroll
                for (int v = 0; v < 8; v++) acc[u][v] += a[u]*b[v];
        }
        __syncthreads();
    }
    int o8 = o0 + tx*8;
    int h = o8 >> 5, dd = o8 & 31;
#pragma unroll
    for (int u = 0; u < 8; u++) {
        int m = m0 + ty*8 + u;
        int n = m / L, g = m % L;
        float* dst = &OUT[(((size_t)(n*HN + h))*L + g)*HDM + dd];
        *(float4*)dst       = make_float4(acc[u][0], acc[u][1], acc[u][2], acc[u][3]);
        *(float4*)(dst + 4) = make_float4(acc[u][4], acc[u][5], acc[u][6], acc[u][7]);
    }
}

// ---------------- dp logits GEMM + mask + exp -> E (fp32) --------------------
// grid (8 j-tiles, 128 slices), 256 threads; tile 128(i) x 64(j), K=32, 8x4 micro.
__global__ __launch_bounds__(256) void k_logits() {
    __shared__ float Qs[32][132];
    __shared__ float Ks[32][68];
    __shared__ float mr[128], mc[64];
    int tid = threadIdx.x;
    int tx = tid & 15, ty = tid >> 4;
    int j0 = blockIdx.x * 64;
    int slice = blockIdx.y;
    int n = slice >> 3;
    const float* q = g_qd + (size_t)slice * GD * HDM;
    const float* k = g_kp + (size_t)slice * GP * HDM;

#pragma unroll
    for (int s = 0; s < 4; s++) {              // Q: 128x32 = 1024 float4
        int f = tid + s*256;
        int row = f >> 3, c4 = f & 7;
        float4 v = *(const float4*)&q[(size_t)row*HDM + c4*4];
        Qs[c4*4+0][row] = v.x; Qs[c4*4+1][row] = v.y;
        Qs[c4*4+2][row] = v.z; Qs[c4*4+3][row] = v.w;
    }
#pragma unroll
    for (int s = 0; s < 2; s++) {              // K tile: 64x32 = 512 float4
        int f = tid + s*256;
        int row = f >> 3, c4 = f & 7;
        float4 v = *(const float4*)&k[(size_t)(j0+row)*HDM + c4*4];
        Ks[c4*4+0][row] = v.x; Ks[c4*4+1][row] = v.y;
        Ks[c4*4+2][row] = v.z; Ks[c4*4+3][row] = v.w;
    }
    if (tid < 128) mr[tid] = g_md[n*GD + tid];
    if (tid < 64)  mc[tid] = g_mp[n*GP + j0 + tid];
    __syncthreads();

    float acc[8][4];
#pragma unroll
    for (int u = 0; u < 8; u++)
#pragma unroll
        for (int v = 0; v < 4; v++) acc[u][v] = 0.0f;
#pragma unroll
    for (int kk = 0; kk < 32; kk++) {
        float4 a0 = *(const float4*)&Qs[kk][ty*8];
        float4 a1 = *(const float4*)&Qs[kk][ty*8+4];
        float4 b  = *(const float4*)&Ks[kk][tx*4];
        float a[8] = {a0.x,a0.y,a0.z,a0.w,a1.x,a1.y,a1.z,a1.w};
        float bb[4] = {b.x,b.y,b.z,b.w};
#pragma unroll
        for (int u = 0; u < 8; u++)
#pragma unroll
            for (int v = 0; v < 4; v++) acc[u][v] += a[u]*bb[v];
    }
#pragma unroll
    for (int u = 0; u < 8; u++) {
        int i = ty*8 + u;
        float rm = mr[i];
        float4 o;
        o.x = (rm * mc[tx*4+0] > 0.0f) ? exp2f(acc[u][0]*EXPSC) : 0.0f;
        o.y = (rm * mc[tx*4+1] > 0.0f) ? exp2f(acc[u][1]*EXPSC) : 0.0f;
        o.z = (rm * mc[tx*4+2] > 0.0f) ? exp2f(acc[u][2]*EXPSC) : 0.0f;
        o.w = (rm * mc[tx*4+3] > 0.0f) ? exp2f(acc[u][3]*EXPSC) : 0.0f;
        *(float4*)&g_E[(size_t)slice*GD*GP + (size_t)i*GP + j0 + tx*4] = o;
    }
}

// ---------------- init column sums to 1 (so c=1 on first iteration) ----------
__global__ void k_initc() {
    int i = blockIdx.x * blockDim.x + threadIdx.x;
    if (i < NHS*GP) g_cs[i] = 1.0f;
}

// ---------------- one fused Sinkhorn iteration over the dp pair --------------
// One block per (n,h) slice: 128 rows x 512 cols. 8 warps; lane owns 16 cols.
__global__ __launch_bounds__(256) void k_sink() {
    int slice = blockIdx.x;
    int lane = threadIdx.x & 31, w = threadIdx.x >> 5;
    const float* Es = g_E + (size_t)slice * GD * GP;
    float* cs = g_cs + slice * GP;
    float* rr = g_r  + slice * GD;
    __shared__ float sh[GP];

    float cv[16];
#pragma unroll
    for (int ch = 0; ch < 4; ch++) {
        float4 v = *(const float4*)&cs[ch*128 + lane*4];
        cv[ch*4+0] = (v.x > 0.0f) ? 1.0f/v.x : 0.0f;
        cv[ch*4+1] = (v.y > 0.0f) ? 1.0f/v.y : 0.0f;
        cv[ch*4+2] = (v.z > 0.0f) ? 1.0f/v.z : 0.0f;
        cv[ch*4+3] = (v.w > 0.0f) ? 1.0f/v.w : 0.0f;
    }
    for (int i = threadIdx.x; i < GP; i += 256) sh[i] = 0.0f;
    __syncthreads();

    float colacc[16];
#pragma unroll
    for (int u = 0; u < 16; u++) colacc[u] = 0.0f;

    for (int i = w; i < GD; i += 8) {
        const float4* rp = (const float4*)(Es + (size_t)i * GP);
        float ev[16];
        float s = 0.0f;
#pragma unroll
        for (int ch = 0; ch < 4; ch++) {
            float4 v = rp[ch*32 + lane];
            ev[ch*4+0] = v.x; ev[ch*4+1] = v.y; ev[ch*4+2] = v.z; ev[ch*4+3] = v.w;
            s += v.x*cv[ch*4+0] + v.y*cv[ch*4+1] + v.z*cv[ch*4+2] + v.w*cv[ch*4+3];
        }
#pragma unroll
        for (int off = 16; off > 0; off >>= 1) s += __shfl_xor_sync(0xFFFFFFFFu, s, off);
        float r = (s > 0.0f) ? 1.0f/s : 0.0f;
        if (lane == 0) rr[i] = r;
#pragma unroll
        for (int u = 0; u < 16; u++) colacc[u] += r * ev[u];
    }
#pragma unroll
    for (int u = 0; u < 16; u++)
        atomicAdd(&sh[(u >> 2)*128 + lane*4 + (u & 3)], colacc[u]);
    __syncthreads();
    for (int i = threadIdx.x; i < GP; i += 256) cs[i] = sh[i];
}

// ---------------- write a_dp = diag(r) E diag(c) in [n,i,j,h] layout ----------
__global__ __launch_bounds__(256) void k_adp(float* __restrict__ out) {
    __shared__ float sh[8][516];
    __shared__ float csh[GP];
    __shared__ float rsh[8];
    int b = blockIdx.x;           // b = n*128 + i
    int n = b >> 7, i = b & 127;
    int tid = threadIdx.x;
    if (tid < 8) rsh[tid] = g_r[(n*8 + tid)*GD + i];
    for (int j = tid; j < GP; j += 256) {
        float c = g_cs[(size_t)(n*8)*GP + 0];  // placeholder to keep compiler honest (unused)
        (void)c;
    }
#pragma unroll
    for (int h = 0; h < 8; h++)
        for (int j = tid; j < GP; j += 256)
            sh[h][j] = g_E[((size_t)(n*8 + h)*GD + i)*GP + j];
    // per-(h) column sums share the same slice index: load all 8 h's c-vectors?
    // c depends on (h, j): csh must be per-h -> compute on the fly instead.
    __syncthreads();
    float* dst = out + (size_t)b * GP * 8;
#pragma unroll
    for (int t = 0; t < 16; t++) {
        int o = t*256 + tid;
        int j = o >> 3, h = o & 7;
        float csv = g_cs[(n*8 + h)*GP + j];
        float c = (csv > 0.0f) ? 1.0f/csv : 0.0f;
        dst[o] = rsh[h] * sh[h][j] * c;
    }
    (void)csh;
}

// ---------------- query embedding (exact closed form) ------------------------
// embed numerator u[n,o] = sp[n,:]·Wv_p[o,:] + sd[n,:]·Wv_d[o,:]
__global__ __launch_bounds__(256) void k_vembed(const float* __restrict__ Wvp,
                                                const float* __restrict__ Wvd,
                                                float* __restrict__ out) {
    __shared__ float sp[DM], sd[DM];
    int n = blockIdx.x;
    int tid = threadIdx.x, lane = tid & 31, w = tid >> 5;
    sp[tid] = g_sp[n*DM + tid];
    sd[tid] = g_sd[n*DM + tid];
    __syncthreads();
    float cp = g_cnt[n], cd = g_cnt[NB + n];
    for (int o = w; o < DM; o += 8) {
        float acc = 0.0f;
#pragma unroll
        for (int t = 0; t < 8; t++) {
            int k = lane + t*32;
            acc += sp[k]*Wvp[(size_t)o*DM + k] + sd[k]*Wvd[(size_t)o*DM + k];
        }
#pragma unroll
        for (int off = 16; off > 0; off >>= 1) acc += __shfl_xor_sync(0xFFFFFFFFu, acc, off);
        if (lane == 0) {
            out[(size_t)n*512 + o]       = 0.5f * acc / cp;
            out[(size_t)n*512 + 256 + o] = 0.5f * acc / cd;
        }
    }
}

// ---------------- launch ------------------------------------------------------
extern "C" void kernel_launch(void* const* d_in, const int* in_sizes, int n_in,
                              void* d_out, int out_size) {
    const float* protein = (const float*)d_in[0];
    const float* drug    = (const float*)d_in[1];
    const void*  maskp   = d_in[2];
    const void*  maskd   = d_in[3];
    const float* Wk_p    = (const float*)d_in[5];
    const float* Wv_p    = (const float*)d_in[6];
    const float* Wq_d    = (const float*)d_in[7];
    const float* Wv_d    = (const float*)d_in[9];
    float* out = (float*)d_out;

    // defensive output layout: (query_embed[16,512], a_dp[16,128,512,8]) flattened
    size_t adp_elems = (size_t)NB * GD * GP * HN;          // 8388608
    bool write_q   = ((size_t)out_size > adp_elems) || ((size_t)out_size < adp_elems);
    bool write_adp = ((size_t)out_size >= adp_elems);
    size_t adp_off = ((size_t)out_size >= adp_elems + NB*512) ? (size_t)NB*512 : 0;

    k_probe<<<1, 32>>>((const unsigned int*)maskp);
    k_group<<<NB*GP, 256>>>(protein, maskp, GP, 0);
    k_group<<<NB*GD, 256>>>(drug,    maskd, GD, 1);
    k_msum<<<dim3(NB, 2), 256>>>();
    k_proj<<<dim3(64, 2, 2), 256>>>(Wk_p, Wq_d);
    if (write_q) k_vembed<<<NB, 256>>>(Wv_p, Wv_d, out);
    if (write_adp) {
        k_logits<<<dim3(8, NHS), 256>>>();
        k_initc<<<(NHS*GP + 255)/256, 256>>>();
        for (int it = 0; it < 4; it++) k_sink<<<NHS, 256>>>();
        k_adp<<<NB*GD, 256>>>(out + adp_off);
    }
}

// round 4
// speedup vs baseline: 1.1693x; 1.1693x over previous
#include <cuda_runtime.h>
#include <cuda_fp16.h>
#include <cuda_bf16.h>
#include <cstdint>

// ---------------- problem constants ----------------
#define NB  16
#define HN  8
#define HDM 32
#define DM  256
#define GP  512
#define GD  128
#define NHS 128          // NB*HN slices
// (1/sqrt(32)) * log2(e)
#define EXPSC 0.2550526808750678f

// ---------------- scratch (static device globals; no runtime alloc) ----------------
__device__ float  g_pg[NB*GP*DM];        // grouped protein  [n*GP+g][256]
__device__ float  g_dg[NB*GD*DM];        // grouped drug
__device__ float  g_mp[NB*GP];           // protein group mask (0/1)
__device__ float  g_md[NB*GD];           // drug group mask
__device__ float  g_part[2*NB*8*DM];     // partial masked sums [ent][n][seg][d]
__device__ float  g_cpart[2*NB*8];       // partial counts
__device__ float  g_sp[NB*DM];           // masked sum grouped protein
__device__ float  g_sd[NB*DM];           // masked sum grouped drug
__device__ float  g_cnt[2*NB];           // valid-group counts
__device__ float  g_kp[NHS*GP*HDM];      // K_protein [(n*8+h)*512 + j][32]
__device__ float  g_qd[NHS*GD*HDM];      // Q_drug    [(n*8+h)*128 + i][32]
__device__ __half g_E [NHS*GD*GP];       // E = valid*exp(scaled logits), fp16
__device__ float  g_r [NHS*GD];          // final row scalings
__device__ float  g_c [NHS*GP];          // final column scalings (reciprocals)
__device__ int    g_maskmode;

// ---------------- mask dtype probe ----------------
__global__ void k_probe(const unsigned int* __restrict__ m) {
    if (threadIdx.x != 0 || blockIdx.x != 0) return;
    int cbf = 0, cf = 0, ch16 = 0, big = 0;
    for (int i = 0; i < 256; i++) {
        unsigned w = m[i];
        cbf  += (w == 0x3F803F80u);
        cf   += (w == 0x3F800000u);
        ch16 += (w == 0x3C003C00u);
        big  += (w > 1u);
    }
    int mode;
    if (cbf >= 4)       mode = 3;
    else if (ch16 >= 4) mode = 3;
    else if (cf >= 4)   mode = 0;
    else if (big > 0)   mode = 2;
    else                mode = 1;
    g_maskmode = mode;
}

__device__ __forceinline__ float mask_at(const void* M, int tok, int mode) {
    switch (mode) {
        case 0:  return ((const float*)M)[tok] != 0.0f ? 1.0f : 0.0f;
        case 1:  return ((const int*)M)[tok]   != 0    ? 1.0f : 0.0f;
        case 2:  return ((const unsigned char*)M)[tok] ? 1.0f : 0.0f;
        default: return ((const unsigned short*)M)[tok] ? 1.0f : 0.0f;
    }
}

// ---------------- grouping: mean over GS=4 tokens + any() mask ----------------
__global__ void k_group(const float* __restrict__ X, const void* __restrict__ M,
                        int G, int isDrug) {
    int b = blockIdx.x;          // b = n*G + g
    int d = threadIdx.x;
    const float* src = X + (size_t)b * 4 * DM;
    float v = 0.25f * (src[d] + src[DM + d] + src[2*DM + d] + src[3*DM + d]);
    float* out = isDrug ? g_dg : g_pg;
    out[(size_t)b * DM + d] = v;
    if (d == 0) {
        int mode = g_maskmode;
        float m = mask_at(M, 4*b+0, mode) + mask_at(M, 4*b+1, mode)
                + mask_at(M, 4*b+2, mode) + mask_at(M, 4*b+3, mode);
        (isDrug ? g_md : g_mp)[b] = (m > 0.0f) ? 1.0f : 0.0f;
    }
}

// ---------------- masked sums, stage 1: partials over G/8 segments ------------
__global__ __launch_bounds__(256) void k_msum2() {
    int n = blockIdx.x, ent = blockIdx.y, seg = blockIdx.z;
    int d = threadIdx.x;
    const float* X = ent ? g_dg : g_pg;
    const float* m = ent ? g_md : g_mp;
    int G = ent ? GD : GP;
    int chunk = G >> 3;
    int g0 = seg * chunk;
    float acc = 0.0f;
    for (int g = g0; g < g0 + chunk; g++)
        acc += m[n*G + g] * X[((size_t)(n*G + g))*DM + d];
    g_part[((ent*NB + n)*8 + seg)*DM + d] = acc;
    if (d == 0) {
        float c = 0.0f;
        for (int g = g0; g < g0 + chunk; g++) c += m[n*G + g];
        g_cpart[(ent*NB + n)*8 + seg] = c;
    }
}

// ---------------- masked sums, stage 2: finish ---------------------------------
__global__ void k_msumf() {
    int n = blockIdx.x, ent = blockIdx.y, d = threadIdx.x;
    float acc = 0.0f;
#pragma unroll
    for (int s = 0; s < 8; s++)
        acc += g_part[((ent*NB + n)*8 + s)*DM + d];
    (ent ? g_sd : g_sp)[n*DM + d] = acc;
    if (d == 0) {
        float c = 0.0f;
#pragma unroll
        for (int s = 0; s < 8; s++) c += g_cpart[(ent*NB + n)*8 + s];
        g_cnt[ent*NB + n] = c;
    }
}

// ---------------- projection GEMM: OUT = group(X) @ W^T (head-split layout) ----
__global__ __launch_bounds__(256) void k_proj(const float* __restrict__ Wkp,
                                              const float* __restrict__ Wqd) {
    const float* X; const float* W; float* OUT; int L;
    if (blockIdx.z == 0) { X = g_pg; W = Wkp; OUT = g_kp; L = GP; }
    else                 { if (blockIdx.x >= 16) return;
                           X = g_dg; W = Wqd; OUT = g_qd; L = GD; }
    __shared__ float Xs[16][132];
    __shared__ float Ws[16][132];
    int tid = threadIdx.x;
    int tx = tid & 15, ty = tid >> 4;
    int m0 = blockIdx.x * 128, o0 = blockIdx.y * 128;

    float acc[8][8];
#pragma unroll
    for (int u = 0; u < 8; u++)
#pragma unroll
        for (int v = 0; v < 8; v++) acc[u][v] = 0.0f;

    for (int k0 = 0; k0 < 256; k0 += 16) {
#pragma unroll
        for (int s = 0; s < 2; s++) {
            int f = tid + s*256;
            int row = f >> 2, c4 = f & 3;
            float4 vx = *(const float4*)&X[(size_t)(m0+row)*256 + k0 + c4*4];
            Xs[c4*4+0][row] = vx.x; Xs[c4*4+1][row] = vx.y;
            Xs[c4*4+2][row] = vx.z; Xs[c4*4+3][row] = vx.w;
            float4 vw = *(const float4*)&W[(size_t)(o0+row)*256 + k0 + c4*4];
            Ws[c4*4+0][row] = vw.x; Ws[c4*4+1][row] = vw.y;
            Ws[c4*4+2][row] = vw.z; Ws[c4*4+3][row] = vw.w;
        }
        __syncthreads();
#pragma unroll
        for (int kk = 0; kk < 16; kk++) {
            float4 a0 = *(const float4*)&Xs[kk][ty*8];
            float4 a1 = *(const float4*)&Xs[kk][ty*8+4];
            float4 b0 = *(const float4*)&Ws[kk][tx*8];
            float4 b1 = *(const float4*)&Ws[kk][tx*8+4];
            float a[8] = {a0.x,a0.y,a0.z,a0.w,a1.x,a1.y,a1.z,a1.w};
            float b[8] = {b0.x,b0.y,b0.z,b0.w,b1.x,b1.y,b1.z,b1.w};
#pragma unroll
            for (int u = 0; u < 8; u++)
#pragma unroll
                for (int v = 0; v < 8; v++) acc[u][v] += a[u]*b[v];
        }
        __syncthreads();
    }
    int o8 = o0 + tx*8;
    int h = o8 >> 5, dd = o8 & 31;
#pragma unroll
    for (int u = 0; u < 8; u++) {
        int m = m0 + ty*8 + u;
        int n = m / L, g = m % L;
        float* dst = &OUT[(((size_t)(n*HN + h))*L + g)*HDM + dd];
        *(float4*)dst       = make_float4(acc[u][0], acc[u][1], acc[u][2], acc[u][3]);
        *(float4*)(dst + 4) = make_float4(acc[u][4], acc[u][5], acc[u][6], acc[u][7]);
    }
}

// ---------------- dp logits GEMM + mask + exp -> E (fp16) --------------------
__global__ __launch_bounds__(256) void k_logits() {
    __shared__ float Qs[32][132];
    __shared__ float Ks[32][68];
    __shared__ float mr[128], mc[64];
    int tid = threadIdx.x;
    int tx = tid & 15, ty = tid >> 4;
    int j0 = blockIdx.x * 64;
    int slice = blockIdx.y;
    int n = slice >> 3;
    const float* q = g_qd + (size_t)slice * GD * HDM;
    const float* k = g_kp + (size_t)slice * GP * HDM;

#pragma unroll
    for (int s = 0; s < 4; s++) {
        int f = tid + s*256;
        int row = f >> 3, c4 = f & 7;
        float4 v = *(const float4*)&q[(size_t)row*HDM + c4*4];
        Qs[c4*4+0][row] = v.x; Qs[c4*4+1][row] = v.y;
        Qs[c4*4+2][row] = v.z; Qs[c4*4+3][row] = v.w;
    }
#pragma unroll
    for (int s = 0; s < 2; s++) {
        int f = tid + s*256;
        int row = f >> 3, c4 = f & 7;
        float4 v = *(const float4*)&k[(size_t)(j0+row)*HDM + c4*4];
        Ks[c4*4+0][row] = v.x; Ks[c4*4+1][row] = v.y;
        Ks[c4*4+2][row] = v.z; Ks[c4*4+3][row] = v.w;
    }
    if (tid < 128) mr[tid] = g_md[n*GD + tid];
    if (tid < 64)  mc[tid] = g_mp[n*GP + j0 + tid];
    __syncthreads();

    float acc[8][4];
#pragma unroll
    for (int u = 0; u < 8; u++)
#pragma unroll
        for (int v = 0; v < 4; v++) acc[u][v] = 0.0f;
#pragma unroll
    for (int kk = 0; kk < 32; kk++) {
        float4 a0 = *(const float4*)&Qs[kk][ty*8];
        float4 a1 = *(const float4*)&Qs[kk][ty*8+4];
        float4 b  = *(const float4*)&Ks[kk][tx*4];
        float a[8] = {a0.x,a0.y,a0.z,a0.w,a1.x,a1.y,a1.z,a1.w};
        float bb[4] = {b.x,b.y,b.z,b.w};
#pragma unroll
        for (int u = 0; u < 8; u++)
#pragma unroll
            for (int v = 0; v < 4; v++) acc[u][v] += a[u]*bb[v];
    }
#pragma unroll
    for (int u = 0; u < 8; u++) {
        int i = ty*8 + u;
        float rm = mr[i];
        float e0 = (rm * mc[tx*4+0] > 0.0f) ? exp2f(acc[u][0]*EXPSC) : 0.0f;
        float e1 = (rm * mc[tx*4+1] > 0.0f) ? exp2f(acc[u][1]*EXPSC) : 0.0f;
        float e2 = (rm * mc[tx*4+2] > 0.0f) ? exp2f(acc[u][2]*EXPSC) : 0.0f;
        float e3 = (rm * mc[tx*4+3] > 0.0f) ? exp2f(acc[u][3]*EXPSC) : 0.0f;
        __half2 h01 = __floats2half2_rn(e0, e1);
        __half2 h23 = __floats2half2_rn(e2, e3);
        __half2* dst = (__half2*)&g_E[(size_t)slice*GD*GP + (size_t)i*GP + j0 + tx*4];
        dst[0] = h01; dst[1] = h23;
    }
}

// ---------------- fused 4-iteration Sinkhorn over the dp pair -----------------
// One block per (n,h) slice: 128 rows x 512 cols. 512 threads (16 warps).
// Column ownership per lane: cols ch*256 + lane*8 + q, ch in {0,1}, q in 0..7.
__global__ __launch_bounds__(512) void k_sink4() {
    int slice = blockIdx.x;
    int tid = threadIdx.x, lane = tid & 31, w = tid >> 5;
    const __half* Es = g_E + (size_t)slice * GD * GP;
    __shared__ float sh[GP];

    float cv[16];
#pragma unroll
    for (int u = 0; u < 16; u++) cv[u] = 1.0f;

    for (int iter = 0; iter < 4; iter++) {
        for (int i = tid; i < GP; i += 512) sh[i] = 0.0f;
        __syncthreads();

        float colacc[16];
#pragma unroll
        for (int u = 0; u < 16; u++) colacc[u] = 0.0f;

#pragma unroll
        for (int ridx = 0; ridx < 8; ridx++) {
            int i = w + ridx*16;
            const uint4* rp = (const uint4*)(Es + (size_t)i * GP);
            float ev[16];
            float s = 0.0f;
#pragma unroll
            for (int ch = 0; ch < 2; ch++) {
                uint4 raw = rp[ch*32 + lane];
                float2 f0 = __half22float2(*(__half2*)&raw.x);
                float2 f1 = __half22float2(*(__half2*)&raw.y);
                float2 f2 = __half22float2(*(__half2*)&raw.z);
                float2 f3 = __half22float2(*(__half2*)&raw.w);
                ev[ch*8+0] = f0.x; ev[ch*8+1] = f0.y;
                ev[ch*8+2] = f1.x; ev[ch*8+3] = f1.y;
                ev[ch*8+4] = f2.x; ev[ch*8+5] = f2.y;
                ev[ch*8+6] = f3.x; ev[ch*8+7] = f3.y;
            }
#pragma unroll
            for (int u = 0; u < 16; u++) s += ev[u] * cv[u];
#pragma unroll
            for (int off = 16; off > 0; off >>= 1)
                s += __shfl_xor_sync(0xFFFFFFFFu, s, off);
            float r = (s > 0.0f) ? 1.0f/s : 0.0f;
            if (iter == 3 && lane == 0) g_r[slice*GD + i] = r;
#pragma unroll
            for (int u = 0; u < 16; u++) colacc[u] += r * ev[u];
        }
#pragma unroll
        for (int u = 0; u < 16; u++)
            atomicAdd(&sh[(u >> 3)*256 + lane*8 + (u & 7)], colacc[u]);
        __syncthreads();

        if (iter == 3) {
            for (int i = tid; i < GP; i += 512) {
                float s2 = sh[i];
                g_c[slice*GP + i] = (s2 > 0.0f) ? 1.0f/s2 : 0.0f;
            }
        } else {
#pragma unroll
            for (int u = 0; u < 16; u++) {
                float s2 = sh[(u >> 3)*256 + lane*8 + (u & 7)];
                cv[u] = (s2 > 0.0f) ? 1.0f/s2 : 0.0f;
            }
        }
        __syncthreads();
    }
}

// ---------------- write a_dp = diag(r) E diag(c) in [n,i,j,h] layout ----------
// Block b = n*128 + i.  Stage: 8 E-rows (8x512 halfs = 8KB) + 8 c-vectors
// (8x512 f32 = 16KB) + 8 r scalars.  Output dst[j*8+h].
__global__ __launch_bounds__(256) void k_adp(float* __restrict__ out) {
    __shared__ __half shE[8][512];      // 512 uint4 total
    __shared__ float  csh[8][512];      // 1024 float4 total
    __shared__ float  rsh[8];
    int b = blockIdx.x;           // b = n*128 + i
    int n = b >> 7, i = b & 127;
    int tid = threadIdx.x;

    if (tid < 8) rsh[tid] = g_r[(n*8 + tid)*GD + i];
#pragma unroll
    for (int t = 0; t < 2; t++) {
        int f = t*256 + tid;               // 0..511
        int h = f >> 6, q = f & 63;        // 64 uint4 per 512-half row
        ((uint4*)&shE[h][0])[q] =
            ((const uint4*)(g_E + ((size_t)(n*8 + h)*GD + i)*GP))[q];
    }
#pragma unroll
    for (int t = 0; t < 4; t++) {
        int f = t*256 + tid;               // 0..1023
        int h = f >> 7, j4 = f & 127;      // 128 float4 per 512-float row
        ((float4*)&csh[h][0])[j4] =
            ((const float4*)(g_c + (size_t)(n*8 + h)*GP))[j4];
    }
    __syncthreads();

    float* dst = out + (size_t)b * GP * 8;
#pragma unroll
    for (int t = 0; t < 16; t++) {
        int o = t*256 + tid;
        int j = o >> 3, h = o & 7;
        float e = __half2float(shE[h][j]);
        dst[o] = rsh[h] * e * csh[h][j];
    }
}

// ---------------- query embedding (exact closed form) ------------------------
__global__ __launch_bounds__(256) void k_vembed(const float* __restrict__ Wvp,
                                                const float* __restrict__ Wvd,
                                                float* __restrict__ out) {
    __shared__ float sp[DM], sd[DM];
    int n = blockIdx.x;
    int tid = threadIdx.x, lane = tid & 31, w = tid >> 5;
    sp[tid] = g_sp[n*DM + tid];
    sd[tid] = g_sd[n*DM + tid];
    __syncthreads();
    float cp = g_cnt[n], cd = g_cnt[NB + n];
    for (int o = w; o < DM; o += 8) {
        float acc = 0.0f;
#pragma unroll
        for (int t = 0; t < 8; t++) {
            int k = lane + t*32;
            acc += sp[k]*Wvp[(size_t)o*DM + k] + sd[k]*Wvd[(size_t)o*DM + k];
        }
#pragma unroll
        for (int off = 16; off > 0; off >>= 1) acc += __shfl_xor_sync(0xFFFFFFFFu, acc, off);
        if (lane == 0) {
            out[(size_t)n*512 + o]       = 0.5f * acc / cp;
            out[(size_t)n*512 + 256 + o] = 0.5f * acc / cd;
        }
    }
}

// ---------------- launch ------------------------------------------------------
extern "C" void kernel_launch(void* const* d_in, const int* in_sizes, int n_in,
                              void* d_out, int out_size) {
    const float* protein = (const float*)d_in[0];
    const float* drug    = (const float*)d_in[1];
    const void*  maskp   = d_in[2];
    const void*  maskd   = d_in[3];
    const float* Wk_p    = (const float*)d_in[5];
    const float* Wv_p    = (const float*)d_in[6];
    const float* Wq_d    = (const float*)d_in[7];
    const float* Wv_d    = (const float*)d_in[9];
    float* out = (float*)d_out;

    size_t adp_elems = (size_t)NB * GD * GP * HN;          // 8388608
    bool write_q   = ((size_t)out_size > adp_elems) || ((size_t)out_size < adp_elems);
    bool write_adp = ((size_t)out_size >= adp_elems);
    size_t adp_off = ((size_t)out_size >= adp_elems + NB*512) ? (size_t)NB*512 : 0;

    k_probe<<<1, 32>>>((const unsigned int*)maskp);
    k_group<<<NB*GP, 256>>>(protein, maskp, GP, 0);
    k_group<<<NB*GD, 256>>>(drug,    maskd, GD, 1);
    k_msum2<<<dim3(NB, 2, 8), 256>>>();
    k_msumf<<<dim3(NB, 2), 256>>>();
    k_proj<<<dim3(64, 2, 2), 256>>>(Wk_p, Wq_d);
    if (write_q) k_vembed<<<NB, 256>>>(Wv_p, Wv_d, out);
    if (write_adp) {
        k_logits<<<dim3(8, NHS), 256>>>();
        k_sink4<<<NHS, 512>>>();
        k_adp<<<NB*GD, 256>>>(out + adp_off);
    }
}

// round 5
// speedup vs baseline: 1.3478x; 1.1527x over previous
#include <cuda_runtime.h>
#include <cuda_fp16.h>
#include <cstdint>

// ---------------- problem constants ----------------
#define NB  16
#define HN  8
#define HDM 32
#define DM  256
#define GP  512
#define GD  128
#define NHS 128          // NB*HN slices
#define SEG 16
// (1/sqrt(32)) * log2(e)
#define EXPSC 0.2550526808750678f

// swizzled smem index: conflict-free for the sink4 atomic pattern
#define SIDX(c) ((((c) & 31) * 17) + ((c) >> 5))

// ---------------- scratch (static device globals; no runtime alloc) ------------
__device__ float  g_pg[NB*GP*DM];        // grouped protein  [n*GP+g][256]
__device__ float  g_dg[NB*GD*DM];        // grouped drug
__device__ float  g_mp[NB*GP];           // protein group mask (0/1)
__device__ float  g_md[NB*GD];           // drug group mask
__device__ float  g_part[2*NB*SEG*DM];   // partial masked sums
__device__ float  g_cpart[2*NB*SEG];     // partial counts
__device__ float  g_kp[NHS*GP*HDM];      // K_protein [(n*8+h)*512 + j][32]
__device__ float  g_qd[NHS*GD*HDM];      // Q_drug    [(n*8+h)*128 + i][32]
__device__ __half g_E [NHS*GD*GP];       // E = valid*exp(scaled logits), fp16
__device__ float  g_r [NHS*GD];          // final row scalings
__device__ float  g_c [NHS*GP];          // final column scalings (reciprocals)
__device__ int    g_maskmode;

// ---------------- packed f32x2 helpers (Blackwell FFMA2) ----------------------
__device__ __forceinline__ unsigned long long pack2(float x) {
    unsigned long long r;
    asm("mov.b64 %0, {%1, %1};" : "=l"(r) : "r"(__float_as_uint(x)));
    return r;
}
__device__ __forceinline__ void fma2(unsigned long long& d,
                                     unsigned long long a, unsigned long long b) {
    asm("fma.rn.f32x2 %0, %1, %2, %0;" : "+l"(d) : "l"(a), "l"(b));
}
__device__ __forceinline__ float2 unpack2(unsigned long long v) {
    unsigned lo, hi;
    asm("mov.b64 {%0, %1}, %2;" : "=r"(lo), "=r"(hi) : "l"(v));
    return make_float2(__uint_as_float(lo), __uint_as_float(hi));
}

// ---------------- mask dtype probe (parallel) ----------------------------------
__global__ void k_probe(const unsigned int* __restrict__ m) {
    __shared__ int cnt[4];   // bf16x2/h16x2, f32, big, (unused)
    int t = threadIdx.x;
    if (t < 4) cnt[t] = 0;
    __syncthreads();
    unsigned w = m[t];
    if (w == 0x3F803F80u || w == 0x3C003C00u) atomicAdd(&cnt[0], 1);
    if (w == 0x3F800000u)                     atomicAdd(&cnt[1], 1);
    if (w > 1u)                               atomicAdd(&cnt[2], 1);
    __syncthreads();
    if (t == 0) {
        int mode;
        if (cnt[0] >= 4)      mode = 3;   // 16-bit elements
        else if (cnt[1] >= 4) mode = 0;   // f32
        else if (cnt[2] > 0)  mode = 2;   // u8 bytes
        else                  mode = 1;   // i32
        g_maskmode = mode;
    }
}

__device__ __forceinline__ float mask_at(const void* M, int tok, int mode) {
    switch (mode) {
        case 0:  return ((const float*)M)[tok] != 0.0f ? 1.0f : 0.0f;
        case 1:  return ((const int*)M)[tok]   != 0    ? 1.0f : 0.0f;
        case 2:  return ((const unsigned char*)M)[tok] ? 1.0f : 0.0f;
        default: return ((const unsigned short*)M)[tok] ? 1.0f : 0.0f;
    }
}

// ---------------- grouping: both entities in one launch ------------------------
__global__ void k_group2(const float* __restrict__ P, const float* __restrict__ Dr,
                         const void* __restrict__ MP, const void* __restrict__ MD) {
    int b = blockIdx.x;
    const float* X; const void* M; float* out; float* mout;
    if (b < NB*GP) { X = P;  M = MP; out = g_pg; mout = g_mp; }
    else           { b -= NB*GP; X = Dr; M = MD; out = g_dg; mout = g_md; }
    int d = threadIdx.x;
    const float* src = X + (size_t)b * 4 * DM;
    out[(size_t)b * DM + d] =
        0.25f * (src[d] + src[DM + d] + src[2*DM + d] + src[3*DM + d]);
    if (d == 0) {
        int mode = g_maskmode;
        float m = mask_at(M, 4*b+0, mode) + mask_at(M, 4*b+1, mode)
                + mask_at(M, 4*b+2, mode) + mask_at(M, 4*b+3, mode);
        mout[b] = (m > 0.0f) ? 1.0f : 0.0f;
    }
}

// ---------------- masked sums, stage 1 (16 segments, MLP-4 unroll) -------------
__global__ __launch_bounds__(256) void k_msum2() {
    int n = blockIdx.x, ent = blockIdx.y, seg = blockIdx.z;
    int d = threadIdx.x;
    const float* X = ent ? g_dg : g_pg;
    const float* m = ent ? g_md : g_mp;
    int G = ent ? GD : GP;
    int chunk = G / SEG;                 // 32 or 8
    int g0 = seg * chunk;
    float a0 = 0.f, a1 = 0.f, a2 = 0.f, a3 = 0.f;
    for (int g = g0; g < g0 + chunk; g += 4) {
        a0 += m[n*G+g+0] * X[((size_t)(n*G+g+0))*DM + d];
        a1 += m[n*G+g+1] * X[((size_t)(n*G+g+1))*DM + d];
        a2 += m[n*G+g+2] * X[((size_t)(n*G+g+2))*DM + d];
        a3 += m[n*G+g+3] * X[((size_t)(n*G+g+3))*DM + d];
    }
    g_part[((ent*NB + n)*SEG + seg)*DM + d] = (a0 + a1) + (a2 + a3);
    if (d == 0) {
        float c = 0.0f;
        for (int g = g0; g < g0 + chunk; g++) c += m[n*G + g];
        g_cpart[(ent*NB + n)*SEG + seg] = c;
    }
}

// ---------------- projection GEMM (packed f32x2 FFMA2) -------------------------
__global__ __launch_bounds__(256) void k_proj(const float* __restrict__ Wkp,
                                              const float* __restrict__ Wqd) {
    const float* X; const float* W; float* OUT; int L;
    if (blockIdx.z == 0) { X = g_pg; W = Wkp; OUT = g_kp; L = GP; }
    else                 { if (blockIdx.x >= 16) return;
                           X = g_dg; W = Wqd; OUT = g_qd; L = GD; }
    __shared__ float Xs[16][132];
    __shared__ float Ws[16][132];
    int tid = threadIdx.x;
    int tx = tid & 15, ty = tid >> 4;
    int m0 = blockIdx.x * 128, o0 = blockIdx.y * 128;

    unsigned long long acc2[4][8];       // (row-pair up) x (col v)
#pragma unroll
    for (int u = 0; u < 4; u++)
#pragma unroll
        for (int v = 0; v < 8; v++) acc2[u][v] = 0ULL;

    for (int k0 = 0; k0 < 256; k0 += 16) {
#pragma unroll
        for (int s = 0; s < 2; s++) {
            int f = tid + s*256;
            int row = f >> 2, c4 = f & 3;
            float4 vx = *(const float4*)&X[(size_t)(m0+row)*256 + k0 + c4*4];
            Xs[c4*4+0][row] = vx.x; Xs[c4*4+1][row] = vx.y;
            Xs[c4*4+2][row] = vx.z; Xs[c4*4+3][row] = vx.w;
            float4 vw = *(const float4*)&W[(size_t)(o0+row)*256 + k0 + c4*4];
            Ws[c4*4+0][row] = vw.x; Ws[c4*4+1][row] = vw.y;
            Ws[c4*4+2][row] = vw.z; Ws[c4*4+3][row] = vw.w;
        }
        __syncthreads();
#pragma unroll
        for (int kk = 0; kk < 16; kk++) {
            ulonglong2 ap01 = *(const ulonglong2*)&Xs[kk][ty*8];
            ulonglong2 ap23 = *(const ulonglong2*)&Xs[kk][ty*8 + 4];
            unsigned long long ap[4] = {ap01.x, ap01.y, ap23.x, ap23.y};
            float4 b0 = *(const float4*)&Ws[kk][tx*8];
            float4 b1 = *(const float4*)&Ws[kk][tx*8 + 4];
            unsigned long long bb[8] = {pack2(b0.x), pack2(b0.y), pack2(b0.z), pack2(b0.w),
                                        pack2(b1.x), pack2(b1.y), pack2(b1.z), pack2(b1.w)};
#pragma unroll
            for (int u = 0; u < 4; u++)
#pragma unroll
                for (int v = 0; v < 8; v++) fma2(acc2[u][v], ap[u], bb[v]);
        }
        __syncthreads();
    }
    int o8 = o0 + tx*8;
    int h = o8 >> 5, dd = o8 & 31;
#pragma unroll
    for (int up = 0; up < 4; up++) {
        float r0[8], r1[8];
#pragma unroll
        for (int v = 0; v < 8; v++) {
            float2 p = unpack2(acc2[up][v]);
            r0[v] = p.x; r1[v] = p.y;
        }
#pragma unroll
        for (int half = 0; half < 2; half++) {
            int m = m0 + ty*8 + up*2 + half;
            int n = m / L, g = m % L;
            float* dst = &OUT[(((size_t)(n*HN + h))*L + g)*HDM + dd];
            const float* rr = half ? r1 : r0;
            *(float4*)dst       = make_float4(rr[0], rr[1], rr[2], rr[3]);
            *(float4*)(dst + 4) = make_float4(rr[4], rr[5], rr[6], rr[7]);
        }
    }
}

// ---------------- dp logits GEMM + mask + exp -> E (fp16), packed f32x2 --------
__global__ __launch_bounds__(256) void k_logits() {
    __shared__ float Qs[32][132];
    __shared__ float Ks[32][68];
    __shared__ float mr[128], mc[64];
    int tid = threadIdx.x;
    int tx = tid & 15, ty = tid >> 4;
    int j0 = blockIdx.x * 64;
    int slice = blockIdx.y;
    int n = slice >> 3;
    const float* q = g_qd + (size_t)slice * GD * HDM;
    const float* k = g_kp + (size_t)slice * GP * HDM;

#pragma unroll
    for (int s = 0; s < 4; s++) {
        int f = tid + s*256;
        int row = f >> 3, c4 = f & 7;
        float4 v = *(const float4*)&q[(size_t)row*HDM + c4*4];
        Qs[c4*4+0][row] = v.x; Qs[c4*4+1][row] = v.y;
        Qs[c4*4+2][row] = v.z; Qs[c4*4+3][row] = v.w;
    }
#pragma unroll
    for (int s = 0; s < 2; s++) {
        int f = tid + s*256;
        int row = f >> 3, c4 = f & 7;
        float4 v = *(const float4*)&k[(size_t)(j0+row)*HDM + c4*4];
        Ks[c4*4+0][row] = v.x; Ks[c4*4+1][row] = v.y;
        Ks[c4*4+2][row] = v.z; Ks[c4*4+3][row] = v.w;
    }
    if (tid < 128) mr[tid] = g_md[n*GD + tid];
    if (tid < 64)  mc[tid] = g_mp[n*GP + j0 + tid];
    __syncthreads();

    unsigned long long acc2[4][4];      // (row-pair) x (col)
#pragma unroll
    for (int u = 0; u < 4; u++)
#pragma unroll
        for (int v = 0; v < 4; v++) acc2[u][v] = 0ULL;
#pragma unroll
    for (int kk = 0; kk < 32; kk++) {
        ulonglong2 ap01 = *(const ulonglong2*)&Qs[kk][ty*8];
        ulonglong2 ap23 = *(const ulonglong2*)&Qs[kk][ty*8 + 4];
        unsigned long long ap[4] = {ap01.x, ap01.y, ap23.x, ap23.y};
        float4 b = *(const float4*)&Ks[kk][tx*4];
        unsigned long long bb[4] = {pack2(b.x), pack2(b.y), pack2(b.z), pack2(b.w)};
#pragma unroll
        for (int u = 0; u < 4; u++)
#pragma unroll
            for (int v = 0; v < 4; v++) fma2(acc2[u][v], ap[u], bb[v]);
    }
    float acc[8][4];
#pragma unroll
    for (int up = 0; up < 4; up++)
#pragma unroll
        for (int v = 0; v < 4; v++) {
            float2 p = unpack2(acc2[up][v]);
            acc[up*2][v] = p.x; acc[up*2+1][v] = p.y;
        }
#pragma unroll
    for (int u = 0; u < 8; u++) {
        int i = ty*8 + u;
        float rm = mr[i];
        float e0 = (rm * mc[tx*4+0] > 0.0f) ? exp2f(acc[u][0]*EXPSC) : 0.0f;
        float e1 = (rm * mc[tx*4+1] > 0.0f) ? exp2f(acc[u][1]*EXPSC) : 0.0f;
        float e2 = (rm * mc[tx*4+2] > 0.0f) ? exp2f(acc[u][2]*EXPSC) : 0.0f;
        float e3 = (rm * mc[tx*4+3] > 0.0f) ? exp2f(acc[u][3]*EXPSC) : 0.0f;
        __half2 h01 = __floats2half2_rn(e0, e1);
        __half2 h23 = __floats2half2_rn(e2, e3);
        __half2* dst = (__half2*)&g_E[(size_t)slice*GD*GP + (size_t)i*GP + j0 + tx*4];
        dst[0] = h01; dst[1] = h23;
    }
}

// ---------------- fused 4-iteration Sinkhorn (swizzled, conflict-free) ---------
__global__ __launch_bounds__(512) void k_sink4() {
    int slice = blockIdx.x;
    int tid = threadIdx.x, lane = tid & 31, w = tid >> 5;
    const __half* Es = g_E + (size_t)slice * GD * GP;
    __shared__ float sh[544];

    float cv[16];
#pragma unroll
    for (int u = 0; u < 16; u++) cv[u] = 1.0f;

    for (int iter = 0; iter < 4; iter++) {
        for (int i = tid; i < 544; i += 512) sh[i] = 0.0f;
        __syncthreads();

        float colacc[16];
#pragma unroll
        for (int u = 0; u < 16; u++) colacc[u] = 0.0f;

#pragma unroll
        for (int ridx = 0; ridx < 8; ridx++) {
            int i = w + ridx*16;
            const uint4* rp = (const uint4*)(Es + (size_t)i * GP);
            float ev[16];
            float s = 0.0f;
#pragma unroll
            for (int ch = 0; ch < 2; ch++) {
                uint4 raw = rp[ch*32 + lane];
                float2 f0 = __half22float2(*(__half2*)&raw.x);
                float2 f1 = __half22float2(*(__half2*)&raw.y);
                float2 f2 = __half22float2(*(__half2*)&raw.z);
                float2 f3 = __half22float2(*(__half2*)&raw.w);
                ev[ch*8+0] = f0.x; ev[ch*8+1] = f0.y;
                ev[ch*8+2] = f1.x; ev[ch*8+3] = f1.y;
                ev[ch*8+4] = f2.x; ev[ch*8+5] = f2.y;
                ev[ch*8+6] = f3.x; ev[ch*8+7] = f3.y;
            }
#pragma unroll
            for (int u = 0; u < 16; u++) s += ev[u] * cv[u];
#pragma unroll
            for (int off = 16; off > 0; off >>= 1)
                s += __shfl_xor_sync(0xFFFFFFFFu, s, off);
            float r = (s > 0.0f) ? 1.0f/s : 0.0f;
            if (iter == 3 && lane == 0) g_r[slice*GD + i] = r;
#pragma unroll
            for (int u = 0; u < 16; u++) colacc[u] += r * ev[u];
        }
#pragma unroll
        for (int u = 0; u < 16; u++) {
            int c = (u >> 3)*256 + lane*8 + (u & 7);
            atomicAdd(&sh[SIDX(c)], colacc[u]);
        }
        __syncthreads();

        if (iter == 3) {
            for (int i = tid; i < GP; i += 512) {
                float s2 = sh[SIDX(i)];
                g_c[slice*GP + i] = (s2 > 0.0f) ? 1.0f/s2 : 0.0f;
            }
        } else {
#pragma unroll
            for (int u = 0; u < 16; u++) {
                int c = (u >> 3)*256 + lane*8 + (u & 7);
                float s2 = sh[SIDX(c)];
                cv[u] = (s2 > 0.0f) ? 1.0f/s2 : 0.0f;
            }
        }
        __syncthreads();
    }
}

// ---------------- write a_dp = diag(r) E diag(c) in [n,i,j,h] layout -----------
__global__ __launch_bounds__(256) void k_adp(float* __restrict__ out) {
    __shared__ __half shE[8][512];
    __shared__ float  csh[8][512];
    __shared__ float  rsh[8];
    int b = blockIdx.x;           // b = n*128 + i
    int n = b >> 7, i = b & 127;
    int tid = threadIdx.x;

    if (tid < 8) rsh[tid] = g_r[(n*8 + tid)*GD + i];
#pragma unroll
    for (int t = 0; t < 2; t++) {
        int f = t*256 + tid;               // 0..511
        int h = f >> 6, qq = f & 63;       // 64 uint4 per 512-half row
        ((uint4*)&shE[h][0])[qq] =
            ((const uint4*)(g_E + ((size_t)(n*8 + h)*GD + i)*GP))[qq];
    }
#pragma unroll
    for (int t = 0; t < 4; t++) {
        int f = t*256 + tid;               // 0..1023
        int h = f >> 7, j4 = f & 127;
        ((float4*)&csh[h][0])[j4] =
            ((const float4*)(g_c + (size_t)(n*8 + h)*GP))[j4];
    }
    __syncthreads();

    float* dst = out + (size_t)b * GP * 8;
#pragma unroll
    for (int t = 0; t < 16; t++) {
        int o = t*256 + tid;
        int j = o >> 3, h = o & 7;
        float e = __half2float(shE[h][j]);
        dst[o] = rsh[h] * e * csh[h][j];
    }
}

// ---------------- query embedding (finishes masked sums inline) ----------------
__global__ __launch_bounds__(256) void k_vembed(const float* __restrict__ Wvp,
                                                const float* __restrict__ Wvd,
                                                float* __restrict__ out) {
    __shared__ float sp[DM], sd[DM];
    __shared__ float cnts[2];
    int n = blockIdx.x;
    int tid = threadIdx.x, lane = tid & 31, w = tid >> 5;
    float accp = 0.0f, accd = 0.0f;
#pragma unroll
    for (int s = 0; s < SEG; s++) {
        accp += g_part[((0*NB + n)*SEG + s)*DM + tid];
        accd += g_part[((1*NB + n)*SEG + s)*DM + tid];
    }
    sp[tid] = accp; sd[tid] = accd;
    if (tid < 2) {
        float c = 0.0f;
#pragma unroll
        for (int s = 0; s < SEG; s++) c += g_cpart[(tid*NB + n)*SEG + s];
        cnts[tid] = c;
    }
    __syncthreads();
    float cp = cnts[0], cd = cnts[1];
    for (int o = w; o < DM; o += 8) {
        float acc = 0.0f;
#pragma unroll
        for (int t = 0; t < 8; t++) {
            int k = lane + t*32;
            acc += sp[k]*Wvp[(size_t)o*DM + k] + sd[k]*Wvd[(size_t)o*DM + k];
        }
#pragma unroll
        for (int off = 16; off > 0; off >>= 1) acc += __shfl_xor_sync(0xFFFFFFFFu, acc, off);
        if (lane == 0) {
            out[(size_t)n*512 + o]       = 0.5f * acc / cp;
            out[(size_t)n*512 + 256 + o] = 0.5f * acc / cd;
        }
    }
}

// ---------------- launch ---------------------------------------------------------
extern "C" void kernel_launch(void* const* d_in, const int* in_sizes, int n_in,
                              void* d_out, int out_size) {
    const float* protein = (const float*)d_in[0];
    const float* drug    = (const float*)d_in[1];
    const void*  maskp   = d_in[2];
    const void*  maskd   = d_in[3];
    const float* Wk_p    = (const float*)d_in[5];
    const float* Wv_p    = (const float*)d_in[6];
    const float* Wq_d    = (const float*)d_in[7];
    const float* Wv_d    = (const float*)d_in[9];
    float* out = (float*)d_out;

    size_t adp_elems = (size_t)NB * GD * GP * HN;          // 8388608
    bool write_q   = ((size_t)out_size > adp_elems) || ((size_t)out_size < adp_elems);
    bool write_adp = ((size_t)out_size >= adp_elems);
    size_t adp_off = ((size_t)out_size >= adp_elems + NB*512) ? (size_t)NB*512 : 0;

    k_probe<<<1, 256>>>((const unsigned int*)maskp);
    k_group2<<<NB*GP + NB*GD, 256>>>(protein, drug, maskp, maskd);
    k_msum2<<<dim3(NB, 2, SEG), 256>>>();
    k_proj<<<dim3(64, 2, 2), 256>>>(Wk_p, Wq_d);
    if (write_q) k_vembed<<<NB, 256>>>(Wv_p, Wv_d, out);
    if (write_adp) {
        k_logits<<<dim3(8, NHS), 256>>>();
        k_sink4<<<NHS, 512>>>();
        k_adp<<<NB*GD, 256>>>(out + adp_off);
    }
}

// round 6
// speedup vs baseline: 1.4303x; 1.0612x over previous
#include <cuda_runtime.h>
#include <cuda_fp16.h>
#include <cstdint>

// ---------------- problem constants ----------------
#define NB  16
#define HN  8
#define HDM 32
#define DM  256
#define GP  512
#define GD  128
#define NHS 128          // NB*HN slices
#define SEG 16
// (1/sqrt(32)) * log2(e)
#define EXPSC 0.2550526808750678f

// swizzled smem index: conflict-free for the sink4 atomic pattern
#define SIDX(c) ((((c) & 31) * 17) + ((c) >> 5))

// ---------------- scratch (static device globals; no runtime alloc) ------------
__device__ float  g_pg[NB*GP*DM];        // grouped protein  [n*GP+g][256]
__device__ float  g_dg[NB*GD*DM];        // grouped drug
__device__ float  g_mp[NB*GP];           // protein group mask (0/1)
__device__ float  g_md[NB*GD];           // drug group mask
__device__ float  g_part[2*NB*SEG*DM];   // partial masked sums
__device__ float  g_cpart[2*NB*SEG];     // partial counts
__device__ float  g_kp[NHS*GP*HDM];      // K_protein [(n*8+h)*512 + j][32]
__device__ float  g_qd[NHS*GD*HDM];      // Q_drug    [(n*8+h)*128 + i][32]
__device__ __half g_E [NHS*GD*GP];       // E = valid*exp(scaled logits), fp16
__device__ float  g_r [NHS*GD];          // final row scalings
__device__ float  g_c [NHS*GP];          // final column scalings (reciprocals)
__device__ int    g_maskmode;

// ---------------- packed f32x2 helpers (Blackwell FFMA2) ----------------------
__device__ __forceinline__ unsigned long long pack2(float x) {
    unsigned long long r;
    asm("mov.b64 %0, {%1, %1};" : "=l"(r) : "r"(__float_as_uint(x)));
    return r;
}
__device__ __forceinline__ void fma2(unsigned long long& d,
                                     unsigned long long a, unsigned long long b) {
    asm("fma.rn.f32x2 %0, %1, %2, %0;" : "+l"(d) : "l"(a), "l"(b));
}
__device__ __forceinline__ float2 unpack2(unsigned long long v) {
    unsigned lo, hi;
    asm("mov.b64 {%0, %1}, %2;" : "=r"(lo), "=r"(hi) : "l"(v));
    return make_float2(__uint_as_float(lo), __uint_as_float(hi));
}

// ---------------- tf32 split + mma helpers -------------------------------------
__device__ __forceinline__ void tf32split(float x, uint32_t& hi, uint32_t& lo) {
    asm("cvt.rna.tf32.f32 %0, %1;" : "=r"(hi) : "f"(x));
    float r = x - __uint_as_float(hi);
    asm("cvt.rna.tf32.f32 %0, %1;" : "=r"(lo) : "f"(r));
}
__device__ __forceinline__ void mma_tf32(float& c0, float& c1, float& c2, float& c3,
                                         uint32_t a0, uint32_t a1, uint32_t a2, uint32_t a3,
                                         uint32_t b0, uint32_t b1) {
    asm volatile(
        "mma.sync.aligned.m16n8k8.row.col.f32.tf32.tf32.f32 "
        "{%0,%1,%2,%3}, {%4,%5,%6,%7}, {%8,%9}, {%0,%1,%2,%3};"
        : "+f"(c0), "+f"(c1), "+f"(c2), "+f"(c3)
        : "r"(a0), "r"(a1), "r"(a2), "r"(a3), "r"(b0), "r"(b1));
}

// ---------------- mask dtype probe (parallel) ----------------------------------
__global__ void k_probe(const unsigned int* __restrict__ m) {
    __shared__ int cnt[4];
    int t = threadIdx.x;
    if (t < 4) cnt[t] = 0;
    __syncthreads();
    unsigned w = m[t];
    if (w == 0x3F803F80u || w == 0x3C003C00u) atomicAdd(&cnt[0], 1);
    if (w == 0x3F800000u)                     atomicAdd(&cnt[1], 1);
    if (w > 1u)                               atomicAdd(&cnt[2], 1);
    __syncthreads();
    if (t == 0) {
        int mode;
        if (cnt[0] >= 4)      mode = 3;
        else if (cnt[1] >= 4) mode = 0;
        else if (cnt[2] > 0)  mode = 2;
        else                  mode = 1;
        g_maskmode = mode;
    }
}

__device__ __forceinline__ float mask_at(const void* M, int tok, int mode) {
    switch (mode) {
        case 0:  return ((const float*)M)[tok] != 0.0f ? 1.0f : 0.0f;
        case 1:  return ((const int*)M)[tok]   != 0    ? 1.0f : 0.0f;
        case 2:  return ((const unsigned char*)M)[tok] ? 1.0f : 0.0f;
        default: return ((const unsigned short*)M)[tok] ? 1.0f : 0.0f;
    }
}

// ---------------- grouping: both entities in one launch ------------------------
__global__ void k_group2(const float* __restrict__ P, const float* __restrict__ Dr,
                         const void* __restrict__ MP, const void* __restrict__ MD) {
    int b = blockIdx.x;
    const float* X; const void* M; float* out; float* mout;
    if (b < NB*GP) { X = P;  M = MP; out = g_pg; mout = g_mp; }
    else           { b -= NB*GP; X = Dr; M = MD; out = g_dg; mout = g_md; }
    int d = threadIdx.x;
    const float* src = X + (size_t)b * 4 * DM;
    out[(size_t)b * DM + d] =
        0.25f * (src[d] + src[DM + d] + src[2*DM + d] + src[3*DM + d]);
    if (d == 0) {
        int mode = g_maskmode;
        float m = mask_at(M, 4*b+0, mode) + mask_at(M, 4*b+1, mode)
                + mask_at(M, 4*b+2, mode) + mask_at(M, 4*b+3, mode);
        mout[b] = (m > 0.0f) ? 1.0f : 0.0f;
    }
}

// ---------------- masked sums, stage 1 -----------------------------------------
__global__ __launch_bounds__(256) void k_msum2() {
    int n = blockIdx.x, ent = blockIdx.y, seg = blockIdx.z;
    int d = threadIdx.x;
    const float* X = ent ? g_dg : g_pg;
    const float* m = ent ? g_md : g_mp;
    int G = ent ? GD : GP;
    int chunk = G / SEG;
    int g0 = seg * chunk;
    float a0 = 0.f, a1 = 0.f, a2 = 0.f, a3 = 0.f;
    for (int g = g0; g < g0 + chunk; g += 4) {
        a0 += m[n*G+g+0] * X[((size_t)(n*G+g+0))*DM + d];
        a1 += m[n*G+g+1] * X[((size_t)(n*G+g+1))*DM + d];
        a2 += m[n*G+g+2] * X[((size_t)(n*G+g+2))*DM + d];
        a3 += m[n*G+g+3] * X[((size_t)(n*G+g+3))*DM + d];
    }
    g_part[((ent*NB + n)*SEG + seg)*DM + d] = (a0 + a1) + (a2 + a3);
    if (d == 0) {
        float c = 0.0f;
        for (int g = g0; g < g0 + chunk; g++) c += m[n*G + g];
        g_cpart[(ent*NB + n)*SEG + seg] = c;
    }
}

// ---------------- projection GEMM: 3xTF32 tensor-core --------------------------
// CTA tile 128(M) x 64(N), 8 warps as 4(M) x 2(N), warp tile 32x32.
// K loop: steps of 16 (two k8 mma halves). A,B split hi/lo at smem-fill.
#define ASTR 136
#define BSTR 72
__global__ __launch_bounds__(256) void k_proj(const float* __restrict__ Wkp,
                                              const float* __restrict__ Wqd) {
    const float* X; const float* W; float* OUT; int L;
    if (blockIdx.z == 0) { X = g_pg; W = Wkp; OUT = g_kp; L = GP; }
    else                 { if (blockIdx.x >= 16) return;
                           X = g_dg; W = Wqd; OUT = g_qd; L = GD; }
    __shared__ uint32_t AsH[16*ASTR], AsL[16*ASTR];
    __shared__ uint32_t BsH[16*BSTR], BsL[16*BSTR];

    int tid = threadIdx.x;
    int lane = tid & 31, w = tid >> 5;
    int g = lane >> 2, tk = lane & 3;
    int wm = (w & 3) * 32, wn = (w >> 2) * 32;   // warp origin in CTA tile
    int m0 = blockIdx.x * 128, o0 = blockIdx.y * 64;

    float c[2][4][4];
#pragma unroll
    for (int mi = 0; mi < 2; mi++)
#pragma unroll
        for (int ni = 0; ni < 4; ni++)
#pragma unroll
            for (int r = 0; r < 4; r++) c[mi][ni][r] = 0.0f;

    for (int k0 = 0; k0 < 256; k0 += 16) {
        // A tile: 128 x 16 -> 512 float4, 2 per thread
#pragma unroll
        for (int s = 0; s < 2; s++) {
            int f = tid + s*256;
            int row = f >> 2, c4 = f & 3;
            float4 v = *(const float4*)&X[(size_t)(m0+row)*256 + k0 + c4*4];
            uint32_t h0,l0,h1,l1,h2,l2,h3,l3;
            tf32split(v.x, h0, l0); tf32split(v.y, h1, l1);
            tf32split(v.z, h2, l2); tf32split(v.w, h3, l3);
            AsH[(c4*4+0)*ASTR + row] = h0; AsL[(c4*4+0)*ASTR + row] = l0;
            AsH[(c4*4+1)*ASTR + row] = h1; AsL[(c4*4+1)*ASTR + row] = l1;
            AsH[(c4*4+2)*ASTR + row] = h2; AsL[(c4*4+2)*ASTR + row] = l2;
            AsH[(c4*4+3)*ASTR + row] = h3; AsL[(c4*4+3)*ASTR + row] = l3;
        }
        // B tile: 64 x 16 -> 256 float4, 1 per thread.  Bs[k][n] = W[o0+n][k0+k]
        {
            int n = tid >> 2, c4 = tid & 3;
            float4 v = *(const float4*)&W[(size_t)(o0+n)*256 + k0 + c4*4];
            uint32_t h0,l0,h1,l1,h2,l2,h3,l3;
            tf32split(v.x, h0, l0); tf32split(v.y, h1, l1);
            tf32split(v.z, h2, l2); tf32split(v.w, h3, l3);
            BsH[(c4*4+0)*BSTR + n] = h0; BsL[(c4*4+0)*BSTR + n] = l0;
            BsH[(c4*4+1)*BSTR + n] = h1; BsL[(c4*4+1)*BSTR + n] = l1;
            BsH[(c4*4+2)*BSTR + n] = h2; BsL[(c4*4+2)*BSTR + n] = l2;
            BsH[(c4*4+3)*BSTR + n] = h3; BsL[(c4*4+3)*BSTR + n] = l3;
        }
        __syncthreads();

#pragma unroll
        for (int kh = 0; kh < 2; kh++) {
            int kb = kh*8;
            uint32_t aH[2][4], aL[2][4];
#pragma unroll
            for (int mi = 0; mi < 2; mi++) {
                int rb = wm + mi*16 + g;
                aH[mi][0] = AsH[(kb+tk  )*ASTR + rb];
                aH[mi][1] = AsH[(kb+tk  )*ASTR + rb + 8];
                aH[mi][2] = AsH[(kb+tk+4)*ASTR + rb];
                aH[mi][3] = AsH[(kb+tk+4)*ASTR + rb + 8];
                aL[mi][0] = AsL[(kb+tk  )*ASTR + rb];
                aL[mi][1] = AsL[(kb+tk  )*ASTR + rb + 8];
                aL[mi][2] = AsL[(kb+tk+4)*ASTR + rb];
                aL[mi][3] = AsL[(kb+tk+4)*ASTR + rb + 8];
            }
            uint32_t bH[4][2], bL[4][2];
#pragma unroll
            for (int ni = 0; ni < 4; ni++) {
                int nb = wn + ni*8 + g;
                bH[ni][0] = BsH[(kb+tk  )*BSTR + nb];
                bH[ni][1] = BsH[(kb+tk+4)*BSTR + nb];
                bL[ni][0] = BsL[(kb+tk  )*BSTR + nb];
                bL[ni][1] = BsL[(kb+tk+4)*BSTR + nb];
            }
#pragma unroll
            for (int mi = 0; mi < 2; mi++)
#pragma unroll
                for (int ni = 0; ni < 4; ni++) {
                    float* cc = c[mi][ni];
                    mma_tf32(cc[0],cc[1],cc[2],cc[3],
                             aH[mi][0],aH[mi][1],aH[mi][2],aH[mi][3],
                             bH[ni][0],bH[ni][1]);
                    mma_tf32(cc[0],cc[1],cc[2],cc[3],
                             aH[mi][0],aH[mi][1],aH[mi][2],aH[mi][3],
                             bL[ni][0],bL[ni][1]);
                    mma_tf32(cc[0],cc[1],cc[2],cc[3],
                             aL[mi][0],aL[mi][1],aL[mi][2],aL[mi][3],
                             bH[ni][0],bH[ni][1]);
                }
        }
        __syncthreads();
    }

    // store: OUT[((nb*HN + h)*L + gg)*HDM + dd], o even -> float2 safe
#pragma unroll
    for (int mi = 0; mi < 2; mi++)
#pragma unroll
        for (int ni = 0; ni < 4; ni++) {
            int o = o0 + wn + ni*8 + 2*tk;
            int h = o >> 5, dd = o & 31;
            int m = m0 + wm + mi*16 + g;
            int nb = m / L, gg = m % L;
            float* dst = &OUT[(((size_t)(nb*HN + h))*L + gg)*HDM + dd];
            *(float2*)dst = make_float2(c[mi][ni][0], c[mi][ni][1]);
            int m2 = m + 8;
            int nb2 = m2 / L, gg2 = m2 % L;
            float* dst2 = &OUT[(((size_t)(nb2*HN + h))*L + gg2)*HDM + dd];
            *(float2*)dst2 = make_float2(c[mi][ni][2], c[mi][ni][3]);
        }
}

// ---------------- dp logits GEMM + mask + exp -> E (fp16), packed f32x2 --------
__global__ __launch_bounds__(256) void k_logits() {
    __shared__ float Qs[32][132];
    __shared__ float Ks[32][68];
    __shared__ float mr[128], mc[64];
    int tid = threadIdx.x;
    int tx = tid & 15, ty = tid >> 4;
    int j0 = blockIdx.x * 64;
    int slice = blockIdx.y;
    int n = slice >> 3;
    const float* q = g_qd + (size_t)slice * GD * HDM;
    const float* k = g_kp + (size_t)slice * GP * HDM;

#pragma unroll
    for (int s = 0; s < 4; s++) {
        int f = tid + s*256;
        int row = f >> 3, c4 = f & 7;
        float4 v = *(const float4*)&q[(size_t)row*HDM + c4*4];
        Qs[c4*4+0][row] = v.x; Qs[c4*4+1][row] = v.y;
        Qs[c4*4+2][row] = v.z; Qs[c4*4+3][row] = v.w;
    }
#pragma unroll
    for (int s = 0; s < 2; s++) {
        int f = tid + s*256;
        int row = f >> 3, c4 = f & 7;
        float4 v = *(const float4*)&k[(size_t)(j0+row)*HDM + c4*4];
        Ks[c4*4+0][row] = v.x; Ks[c4*4+1][row] = v.y;
        Ks[c4*4+2][row] = v.z; Ks[c4*4+3][row] = v.w;
    }
    if (tid < 128) mr[tid] = g_md[n*GD + tid];
    if (tid < 64)  mc[tid] = g_mp[n*GP + j0 + tid];
    __syncthreads();

    unsigned long long acc2[4][4];
#pragma unroll
    for (int u = 0; u < 4; u++)
#pragma unroll
        for (int v = 0; v < 4; v++) acc2[u][v] = 0ULL;
#pragma unroll
    for (int kk = 0; kk < 32; kk++) {
        ulonglong2 ap01 = *(const ulonglong2*)&Qs[kk][ty*8];
        ulonglong2 ap23 = *(const ulonglong2*)&Qs[kk][ty*8 + 4];
        unsigned long long ap[4] = {ap01.x, ap01.y, ap23.x, ap23.y};
        float4 b = *(const float4*)&Ks[kk][tx*4];
        unsigned long long bb[4] = {pack2(b.x), pack2(b.y), pack2(b.z), pack2(b.w)};
#pragma unroll
        for (int u = 0; u < 4; u++)
#pragma unroll
            for (int v = 0; v < 4; v++) fma2(acc2[u][v], ap[u], bb[v]);
    }
    float acc[8][4];
#pragma unroll
    for (int up = 0; up < 4; up++)
#pragma unroll
        for (int v = 0; v < 4; v++) {
            float2 p = unpack2(acc2[up][v]);
            acc[up*2][v] = p.x; acc[up*2+1][v] = p.y;
        }
#pragma unroll
    for (int u = 0; u < 8; u++) {
        int i = ty*8 + u;
        float rm = mr[i];
        float e0 = (rm * mc[tx*4+0] > 0.0f) ? exp2f(acc[u][0]*EXPSC) : 0.0f;
        float e1 = (rm * mc[tx*4+1] > 0.0f) ? exp2f(acc[u][1]*EXPSC) : 0.0f;
        float e2 = (rm * mc[tx*4+2] > 0.0f) ? exp2f(acc[u][2]*EXPSC) : 0.0f;
        float e3 = (rm * mc[tx*4+3] > 0.0f) ? exp2f(acc[u][3]*EXPSC) : 0.0f;
        __half2 h01 = __floats2half2_rn(e0, e1);
        __half2 h23 = __floats2half2_rn(e2, e3);
        __half2* dst = (__half2*)&g_E[(size_t)slice*GD*GP + (size_t)i*GP + j0 + tx*4];
        dst[0] = h01; dst[1] = h23;
    }
}

// ---------------- fused 4-iteration Sinkhorn (swizzled, conflict-free) ---------
__global__ __launch_bounds__(512) void k_sink4() {
    int slice = blockIdx.x;
    int tid = threadIdx.x, lane = tid & 31, w = tid >> 5;
    const __half* Es = g_E + (size_t)slice * GD * GP;
    __shared__ float sh[544];

    float cv[16];
#pragma unroll
    for (int u = 0; u < 16; u++) cv[u] = 1.0f;

    for (int iter = 0; iter < 4; iter++) {
        for (int i = tid; i < 544; i += 512) sh[i] = 0.0f;
        __syncthreads();

        float colacc[16];
#pragma unroll
        for (int u = 0; u < 16; u++) colacc[u] = 0.0f;

#pragma unroll
        for (int ridx = 0; ridx < 8; ridx++) {
            int i = w + ridx*16;
            const uint4* rp = (const uint4*)(Es + (size_t)i * GP);
            float ev[16];
            float s = 0.0f;
#pragma unroll
            for (int ch = 0; ch < 2; ch++) {
                uint4 raw = rp[ch*32 + lane];
                float2 f0 = __half22float2(*(__half2*)&raw.x);
                float2 f1 = __half22float2(*(__half2*)&raw.y);
                float2 f2 = __half22float2(*(__half2*)&raw.z);
                float2 f3 = __half22float2(*(__half2*)&raw.w);
                ev[ch*8+0] = f0.x; ev[ch*8+1] = f0.y;
                ev[ch*8+2] = f1.x; ev[ch*8+3] = f1.y;
                ev[ch*8+4] = f2.x; ev[ch*8+5] = f2.y;
                ev[ch*8+6] = f3.x; ev[ch*8+7] = f3.y;
            }
#pragma unroll
            for (int u = 0; u < 16; u++) s += ev[u] * cv[u];
#pragma unroll
            for (int off = 16; off > 0; off >>= 1)
                s += __shfl_xor_sync(0xFFFFFFFFu, s, off);
            float r = (s > 0.0f) ? 1.0f/s : 0.0f;
            if (iter == 3 && lane == 0) g_r[slice*GD + i] = r;
#pragma unroll
            for (int u = 0; u < 16; u++) colacc[u] += r * ev[u];
        }
#pragma unroll
        for (int u = 0; u < 16; u++) {
            int cc = (u >> 3)*256 + lane*8 + (u & 7);
            atomicAdd(&sh[SIDX(cc)], colacc[u]);
        }
        __syncthreads();

        if (iter == 3) {
            for (int i = tid; i < GP; i += 512) {
                float s2 = sh[SIDX(i)];
                g_c[slice*GP + i] = (s2 > 0.0f) ? 1.0f/s2 : 0.0f;
            }
        } else {
#pragma unroll
            for (int u = 0; u < 16; u++) {
                int cc = (u >> 3)*256 + lane*8 + (u & 7);
                float s2 = sh[SIDX(cc)];
                cv[u] = (s2 > 0.0f) ? 1.0f/s2 : 0.0f;
            }
        }
        __syncthreads();
    }
}

// ---------------- write a_dp = diag(r) E diag(c) in [n,i,j,h] layout -----------
__global__ __launch_bounds__(256) void k_adp(float* __restrict__ out) {
    __shared__ __half shE[8][512];
    __shared__ float  csh[8][512];
    __shared__ float  rsh[8];
    int b = blockIdx.x;           // b = n*128 + i
    int n = b >> 7, i = b & 127;
    int tid = threadIdx.x;

    if (tid < 8) rsh[tid] = g_r[(n*8 + tid)*GD + i];
#pragma unroll
    for (int t = 0; t < 2; t++) {
        int f = t*256 + tid;
        int h = f >> 6, qq = f & 63;
        ((uint4*)&shE[h][0])[qq] =
            ((const uint4*)(g_E + ((size_t)(n*8 + h)*GD + i)*GP))[qq];
    }
#pragma unroll
    for (int t = 0; t < 4; t++) {
        int f = t*256 + tid;
        int h = f >> 7, j4 = f & 127;
        ((float4*)&csh[h][0])[j4] =
            ((const float4*)(g_c + (size_t)(n*8 + h)*GP))[j4];
    }
    __syncthreads();

    float* dst = out + (size_t)b * GP * 8;
#pragma unroll
    for (int t = 0; t < 16; t++) {
        int o = t*256 + tid;
        int j = o >> 3, h = o & 7;
        float e = __half2float(shE[h][j]);
        dst[o] = rsh[h] * e * csh[h][j];
    }
}

// ---------------- query embedding (finishes masked sums inline) ----------------
__global__ __launch_bounds__(256) void k_vembed(const float* __restrict__ Wvp,
                                                const float* __restrict__ Wvd,
                                                float* __restrict__ out) {
    __shared__ float sp[DM], sd[DM];
    __shared__ float cnts[2];
    int n = blockIdx.x;
    int tid = threadIdx.x, lane = tid & 31, w = tid >> 5;
    float accp = 0.0f, accd = 0.0f;
#pragma unroll
    for (int s = 0; s < SEG; s++) {
        accp += g_part[((0*NB + n)*SEG + s)*DM + tid];
        accd += g_part[((1*NB + n)*SEG + s)*DM + tid];
    }
    sp[tid] = accp; sd[tid] = accd;
    if (tid < 2) {
        float c = 0.0f;
#pragma unroll
        for (int s = 0; s < SEG; s++) c += g_cpart[(tid*NB + n)*SEG + s];
        cnts[tid] = c;
    }
    __syncthreads();
    float cp = cnts[0], cd = cnts[1];
    for (int o = w; o < DM; o += 8) {
        float acc = 0.0f;
#pragma unroll
        for (int t = 0; t < 8; t++) {
            int k = lane + t*32;
            acc += sp[k]*Wvp[(size_t)o*DM + k] + sd[k]*Wvd[(size_t)o*DM + k];
        }
#pragma unroll
        for (int off = 16; off > 0; off >>= 1) acc += __shfl_xor_sync(0xFFFFFFFFu, acc, off);
        if (lane == 0) {
            out[(size_t)n*512 + o]       = 0.5f * acc / cp;
            out[(size_t)n*512 + 256 + o] = 0.5f * acc / cd;
        }
    }
}

// ---------------- launch ---------------------------------------------------------
extern "C" void kernel_launch(void* const* d_in, const int* in_sizes, int n_in,
                              void* d_out, int out_size) {
    const float* protein = (const float*)d_in[0];
    const float* drug    = (const float*)d_in[1];
    const void*  maskp   = d_in[2];
    const void*  maskd   = d_in[3];
    const float* Wk_p    = (const float*)d_in[5];
    const float* Wv_p    = (const float*)d_in[6];
    const float* Wq_d    = (const float*)d_in[7];
    const float* Wv_d    = (const float*)d_in[9];
    float* out = (float*)d_out;

    size_t adp_elems = (size_t)NB * GD * GP * HN;          // 8388608
    bool write_q   = ((size_t)out_size > adp_elems) || ((size_t)out_size < adp_elems);
    bool write_adp = ((size_t)out_size >= adp_elems);
    size_t adp_off = ((size_t)out_size >= adp_elems + NB*512) ? (size_t)NB*512 : 0;

    k_probe<<<1, 256>>>((const unsigned int*)maskp);
    k_group2<<<NB*GP + NB*GD, 256>>>(protein, drug, maskp, maskd);
    k_msum2<<<dim3(NB, 2, SEG), 256>>>();
    k_proj<<<dim3(64, 4, 2), 256>>>(Wk_p, Wq_d);
    if (write_q) k_vembed<<<NB, 256>>>(Wv_p, Wv_d, out);
    if (write_adp) {
        k_logits<<<dim3(8, NHS), 256>>>();
        k_sink4<<<NHS, 512>>>();
        k_adp<<<NB*GD, 256>>>(out + adp_off);
    }
}

// round 7
// speedup vs baseline: 1.5814x; 1.1056x over previous
#include <cuda_runtime.h>
#include <cuda_fp16.h>
#include <cstdint>

// ---------------- problem constants ----------------
#define NB  16
#define HN  8
#define HDM 32
#define DM  256
#define GP  512
#define GD  128
#define NHS 128          // NB*HN slices
#define SEG 16
// (1/sqrt(32)) * log2(e)
#define EXPSC 0.2550526808750678f

// swizzled smem index: conflict-free for the sink4 atomic pattern
#define SIDX(c) ((((c) & 31) * 17) + ((c) >> 5))

// ---------------- scratch (static device globals; no runtime alloc) ------------
__device__ float  g_pg[NB*GP*DM];        // grouped protein  [n*GP+g][256]
__device__ float  g_dg[NB*GD*DM];        // grouped drug
__device__ float  g_mp[NB*GP];           // protein group mask (0/1)
__device__ float  g_md[NB*GD];           // drug group mask
__device__ float  g_part[2*NB*SEG*DM];   // partial masked sums
__device__ float  g_cpart[2*NB*SEG];     // partial counts
__device__ float  g_kp[NHS*GP*HDM];      // K_protein [(n*8+h)*512 + j][32]
__device__ float  g_qd[NHS*GD*HDM];      // Q_drug    [(n*8+h)*128 + i][32]
__device__ __half g_E [NHS*GD*GP];       // E = valid*exp(scaled logits), fp16
__device__ float  g_r [NHS*GD];          // final row scalings
__device__ float  g_c [NHS*GP];          // final column scalings (reciprocals)
__device__ int    g_maskmode;

// ---------------- packed f32x2 helpers (Blackwell FFMA2) ----------------------
__device__ __forceinline__ unsigned long long pack2(float x) {
    unsigned long long r;
    asm("mov.b64 %0, {%1, %1};" : "=l"(r) : "r"(__float_as_uint(x)));
    return r;
}
__device__ __forceinline__ void fma2(unsigned long long& d,
                                     unsigned long long a, unsigned long long b) {
    asm("fma.rn.f32x2 %0, %1, %2, %0;" : "+l"(d) : "l"(a), "l"(b));
}
__device__ __forceinline__ float2 unpack2(unsigned long long v) {
    unsigned lo, hi;
    asm("mov.b64 {%0, %1}, %2;" : "=r"(lo), "=r"(hi) : "l"(v));
    return make_float2(__uint_as_float(lo), __uint_as_float(hi));
}

// ---------------- tf32 + mma helpers --------------------------------------------
__device__ __forceinline__ uint32_t tf32cvt(float x) {
    uint32_t r;
    asm("cvt.rna.tf32.f32 %0, %1;" : "=r"(r) : "f"(x));
    return r;
}
__device__ __forceinline__ void mma_tf32(float& c0, float& c1, float& c2, float& c3,
                                         uint32_t a0, uint32_t a1, uint32_t a2, uint32_t a3,
                                         uint32_t b0, uint32_t b1) {
    asm volatile(
        "mma.sync.aligned.m16n8k8.row.col.f32.tf32.tf32.f32 "
        "{%0,%1,%2,%3}, {%4,%5,%6,%7}, {%8,%9}, {%0,%1,%2,%3};"
        : "+f"(c0), "+f"(c1), "+f"(c2), "+f"(c3)
        : "r"(a0), "r"(a1), "r"(a2), "r"(a3), "r"(b0), "r"(b1));
}

// ---------------- mask dtype probe (parallel) ----------------------------------
__global__ void k_probe(const unsigned int* __restrict__ m) {
    __shared__ int cnt[4];
    int t = threadIdx.x;
    if (t < 4) cnt[t] = 0;
    __syncthreads();
    unsigned w = m[t];
    if (w == 0x3F803F80u || w == 0x3C003C00u) atomicAdd(&cnt[0], 1);
    if (w == 0x3F800000u)                     atomicAdd(&cnt[1], 1);
    if (w > 1u)                               atomicAdd(&cnt[2], 1);
    __syncthreads();
    if (t == 0) {
        int mode;
        if (cnt[0] >= 4)      mode = 3;
        else if (cnt[1] >= 4) mode = 0;
        else if (cnt[2] > 0)  mode = 2;
        else                  mode = 1;
        g_maskmode = mode;
    }
}

__device__ __forceinline__ float mask_at(const void* M, int tok, int mode) {
    switch (mode) {
        case 0:  return ((const float*)M)[tok] != 0.0f ? 1.0f : 0.0f;
        case 1:  return ((const int*)M)[tok]   != 0    ? 1.0f : 0.0f;
        case 2:  return ((const unsigned char*)M)[tok] ? 1.0f : 0.0f;
        default: return ((const unsigned short*)M)[tok] ? 1.0f : 0.0f;
    }
}

// ---------------- grouping: both entities in one launch ------------------------
__global__ void k_group2(const float* __restrict__ P, const float* __restrict__ Dr,
                         const void* __restrict__ MP, const void* __restrict__ MD) {
    int b = blockIdx.x;
    const float* X; const void* M; float* out; float* mout;
    if (b < NB*GP) { X = P;  M = MP; out = g_pg; mout = g_mp; }
    else           { b -= NB*GP; X = Dr; M = MD; out = g_dg; mout = g_md; }
    int d = threadIdx.x;
    const float* src = X + (size_t)b * 4 * DM;
    out[(size_t)b * DM + d] =
        0.25f * (src[d] + src[DM + d] + src[2*DM + d] + src[3*DM + d]);
    if (d == 0) {
        int mode = g_maskmode;
        float m = mask_at(M, 4*b+0, mode) + mask_at(M, 4*b+1, mode)
                + mask_at(M, 4*b+2, mode) + mask_at(M, 4*b+3, mode);
        mout[b] = (m > 0.0f) ? 1.0f : 0.0f;
    }
}

// ---------------- masked sums, stage 1 -----------------------------------------
__global__ __launch_bounds__(256) void k_msum2() {
    int n = blockIdx.x, ent = blockIdx.y, seg = blockIdx.z;
    int d = threadIdx.x;
    const float* X = ent ? g_dg : g_pg;
    const float* m = ent ? g_md : g_mp;
    int G = ent ? GD : GP;
    int chunk = G / SEG;
    int g0 = seg * chunk;
    float a0 = 0.f, a1 = 0.f, a2 = 0.f, a3 = 0.f;
    for (int g = g0; g < g0 + chunk; g += 4) {
        a0 += m[n*G+g+0] * X[((size_t)(n*G+g+0))*DM + d];
        a1 += m[n*G+g+1] * X[((size_t)(n*G+g+1))*DM + d];
        a2 += m[n*G+g+2] * X[((size_t)(n*G+g+2))*DM + d];
        a3 += m[n*G+g+3] * X[((size_t)(n*G+g+3))*DM + d];
    }
    g_part[((ent*NB + n)*SEG + seg)*DM + d] = (a0 + a1) + (a2 + a3);
    if (d == 0) {
        float c = 0.0f;
        for (int g = g0; g < g0 + chunk; g++) c += m[n*G + g];
        g_cpart[(ent*NB + n)*SEG + seg] = c;
    }
}

// ---------------- projection GEMM: single-TF32 tensor-core ---------------------
// CTA tile 128(M) x 128(N), 8 warps as 4(M) x 2(N), warp tile 32x64.
// K loop: steps of 16 (two k8 mma halves).
#define ASTR 136
__global__ __launch_bounds__(256) void k_proj(const float* __restrict__ Wkp,
                                              const float* __restrict__ Wqd) {
    const float* X; const float* W; float* OUT; int L;
    if (blockIdx.z == 0) { X = g_pg; W = Wkp; OUT = g_kp; L = GP; }
    else                 { if (blockIdx.x >= 16) return;
                           X = g_dg; W = Wqd; OUT = g_qd; L = GD; }
    __shared__ uint32_t AsH[16*ASTR];
    __shared__ uint32_t BsH[16*ASTR];

    int tid = threadIdx.x;
    int lane = tid & 31, w = tid >> 5;
    int g = lane >> 2, tk = lane & 3;
    int wm = (w & 3) * 32, wn = (w >> 2) * 64;   // warp origin in CTA tile
    int m0 = blockIdx.x * 128, o0 = blockIdx.y * 128;

    float c[2][8][4];
#pragma unroll
    for (int mi = 0; mi < 2; mi++)
#pragma unroll
        for (int ni = 0; ni < 8; ni++)
#pragma unroll
            for (int r = 0; r < 4; r++) c[mi][ni][r] = 0.0f;

    for (int k0 = 0; k0 < 256; k0 += 16) {
        // A and B tiles: each 128 x 16 -> 512 float4, 2 per thread each
#pragma unroll
        for (int s = 0; s < 2; s++) {
            int f = tid + s*256;
            int row = f >> 2, c4 = f & 3;
            float4 va = *(const float4*)&X[(size_t)(m0+row)*256 + k0 + c4*4];
            AsH[(c4*4+0)*ASTR + row] = tf32cvt(va.x);
            AsH[(c4*4+1)*ASTR + row] = tf32cvt(va.y);
            AsH[(c4*4+2)*ASTR + row] = tf32cvt(va.z);
            AsH[(c4*4+3)*ASTR + row] = tf32cvt(va.w);
            float4 vb = *(const float4*)&W[(size_t)(o0+row)*256 + k0 + c4*4];
            BsH[(c4*4+0)*ASTR + row] = tf32cvt(vb.x);
            BsH[(c4*4+1)*ASTR + row] = tf32cvt(vb.y);
            BsH[(c4*4+2)*ASTR + row] = tf32cvt(vb.z);
            BsH[(c4*4+3)*ASTR + row] = tf32cvt(vb.w);
        }
        __syncthreads();

#pragma unroll
        for (int kh = 0; kh < 2; kh++) {
            int kb = kh*8;
            uint32_t aH[2][4];
#pragma unroll
            for (int mi = 0; mi < 2; mi++) {
                int rb = wm + mi*16 + g;
                aH[mi][0] = AsH[(kb+tk  )*ASTR + rb];
                aH[mi][1] = AsH[(kb+tk  )*ASTR + rb + 8];
                aH[mi][2] = AsH[(kb+tk+4)*ASTR + rb];
                aH[mi][3] = AsH[(kb+tk+4)*ASTR + rb + 8];
            }
            uint32_t bH[8][2];
#pragma unroll
            for (int ni = 0; ni < 8; ni++) {
                int nb = wn + ni*8 + g;
                bH[ni][0] = BsH[(kb+tk  )*ASTR + nb];
                bH[ni][1] = BsH[(kb+tk+4)*ASTR + nb];
            }
#pragma unroll
            for (int mi = 0; mi < 2; mi++)
#pragma unroll
                for (int ni = 0; ni < 8; ni++) {
                    float* cc = c[mi][ni];
                    mma_tf32(cc[0],cc[1],cc[2],cc[3],
                             aH[mi][0],aH[mi][1],aH[mi][2],aH[mi][3],
                             bH[ni][0],bH[ni][1]);
                }
        }
        __syncthreads();
    }

    // store: OUT[((nb*HN + h)*L + gg)*HDM + dd]; o even -> float2 aligned
#pragma unroll
    for (int mi = 0; mi < 2; mi++)
#pragma unroll
        for (int ni = 0; ni < 8; ni++) {
            int o = o0 + wn + ni*8 + 2*tk;
            int h = o >> 5, dd = o & 31;
            int m = m0 + wm + mi*16 + g;
            int nb = m / L, gg = m % L;
            float* dst = &OUT[(((size_t)(nb*HN + h))*L + gg)*HDM + dd];
            *(float2*)dst = make_float2(c[mi][ni][0], c[mi][ni][1]);
            int m2 = m + 8;
            int nb2 = m2 / L, gg2 = m2 % L;
            float* dst2 = &OUT[(((size_t)(nb2*HN + h))*L + gg2)*HDM + dd];
            *(float2*)dst2 = make_float2(c[mi][ni][2], c[mi][ni][3]);
        }
}

// ---------------- dp logits GEMM + mask + exp -> E (fp16), packed f32x2 --------
__global__ __launch_bounds__(256) void k_logits() {
    __shared__ float Qs[32][132];
    __shared__ float Ks[32][68];
    __shared__ float mr[128], mc[64];
    int tid = threadIdx.x;
    int tx = tid & 15, ty = tid >> 4;
    int j0 = blockIdx.x * 64;
    int slice = blockIdx.y;
    int n = slice >> 3;
    const float* q = g_qd + (size_t)slice * GD * HDM;
    const float* k = g_kp + (size_t)slice * GP * HDM;

#pragma unroll
    for (int s = 0; s < 4; s++) {
        int f = tid + s*256;
        int row = f >> 3, c4 = f & 7;
        float4 v = *(const float4*)&q[(size_t)row*HDM + c4*4];
        Qs[c4*4+0][row] = v.x; Qs[c4*4+1][row] = v.y;
        Qs[c4*4+2][row] = v.z; Qs[c4*4+3][row] = v.w;
    }
#pragma unroll
    for (int s = 0; s < 2; s++) {
        int f = tid + s*256;
        int row = f >> 3, c4 = f & 7;
        float4 v = *(const float4*)&k[(size_t)(j0+row)*HDM + c4*4];
        Ks[c4*4+0][row] = v.x; Ks[c4*4+1][row] = v.y;
        Ks[c4*4+2][row] = v.z; Ks[c4*4+3][row] = v.w;
    }
    if (tid < 128) mr[tid] = g_md[n*GD + tid];
    if (tid < 64)  mc[tid] = g_mp[n*GP + j0 + tid];
    __syncthreads();

    unsigned long long acc2[4][4];
#pragma unroll
    for (int u = 0; u < 4; u++)
#pragma unroll
        for (int v = 0; v < 4; v++) acc2[u][v] = 0ULL;
#pragma unroll
    for (int kk = 0; kk < 32; kk++) {
        ulonglong2 ap01 = *(const ulonglong2*)&Qs[kk][ty*8];
        ulonglong2 ap23 = *(const ulonglong2*)&Qs[kk][ty*8 + 4];
        unsigned long long ap[4] = {ap01.x, ap01.y, ap23.x, ap23.y};
        float4 b = *(const float4*)&Ks[kk][tx*4];
        unsigned long long bb[4] = {pack2(b.x), pack2(b.y), pack2(b.z), pack2(b.w)};
#pragma unroll
        for (int u = 0; u < 4; u++)
#pragma unroll
            for (int v = 0; v < 4; v++) fma2(acc2[u][v], ap[u], bb[v]);
    }
    float acc[8][4];
#pragma unroll
    for (int up = 0; up < 4; up++)
#pragma unroll
        for (int v = 0; v < 4; v++) {
            float2 p = unpack2(acc2[up][v]);
            acc[up*2][v] = p.x; acc[up*2+1][v] = p.y;
        }
#pragma unroll
    for (int u = 0; u < 8; u++) {
        int i = ty*8 + u;
        float rm = mr[i];
        float e0 = (rm * mc[tx*4+0] > 0.0f) ? exp2f(acc[u][0]*EXPSC) : 0.0f;
        float e1 = (rm * mc[tx*4+1] > 0.0f) ? exp2f(acc[u][1]*EXPSC) : 0.0f;
        float e2 = (rm * mc[tx*4+2] > 0.0f) ? exp2f(acc[u][2]*EXPSC) : 0.0f;
        float e3 = (rm * mc[tx*4+3] > 0.0f) ? exp2f(acc[u][3]*EXPSC) : 0.0f;
        __half2 h01 = __floats2half2_rn(e0, e1);
        __half2 h23 = __floats2half2_rn(e2, e3);
        __half2* dst = (__half2*)&g_E[(size_t)slice*GD*GP + (size_t)i*GP + j0 + tx*4];
        dst[0] = h01; dst[1] = h23;
    }
}

// ---------------- fused 4-iteration Sinkhorn (swizzled, conflict-free) ---------
__global__ __launch_bounds__(512) void k_sink4() {
    int slice = blockIdx.x;
    int tid = threadIdx.x, lane = tid & 31, w = tid >> 5;
    const __half* Es = g_E + (size_t)slice * GD * GP;
    __shared__ float sh[544];

    float cv[16];
#pragma unroll
    for (int u = 0; u < 16; u++) cv[u] = 1.0f;

    for (int iter = 0; iter < 4; iter++) {
        for (int i = tid; i < 544; i += 512) sh[i] = 0.0f;
        __syncthreads();

        float colacc[16];
#pragma unroll
        for (int u = 0; u < 16; u++) colacc[u] = 0.0f;

#pragma unroll
        for (int ridx = 0; ridx < 8; ridx++) {
            int i = w + ridx*16;
            const uint4* rp = (const uint4*)(Es + (size_t)i * GP);
            float ev[16];
            float s = 0.0f;
#pragma unroll
            for (int ch = 0; ch < 2; ch++) {
                uint4 raw = rp[ch*32 + lane];
                float2 f0 = __half22float2(*(__half2*)&raw.x);
                float2 f1 = __half22float2(*(__half2*)&raw.y);
                float2 f2 = __half22float2(*(__half2*)&raw.z);
                float2 f3 = __half22float2(*(__half2*)&raw.w);
                ev[ch*8+0] = f0.x; ev[ch*8+1] = f0.y;
                ev[ch*8+2] = f1.x; ev[ch*8+3] = f1.y;
                ev[ch*8+4] = f2.x; ev[ch*8+5] = f2.y;
                ev[ch*8+6] = f3.x; ev[ch*8+7] = f3.y;
            }
#pragma unroll
            for (int u = 0; u < 16; u++) s += ev[u] * cv[u];
#pragma unroll
            for (int off = 16; off > 0; off >>= 1)
                s += __shfl_xor_sync(0xFFFFFFFFu, s, off);
            float r = (s > 0.0f) ? 1.0f/s : 0.0f;
            if (iter == 3 && lane == 0) g_r[slice*GD + i] = r;
#pragma unroll
            for (int u = 0; u < 16; u++) colacc[u] += r * ev[u];
        }
#pragma unroll
        for (int u = 0; u < 16; u++) {
            int cc = (u >> 3)*256 + lane*8 + (u & 7);
            atomicAdd(&sh[SIDX(cc)], colacc[u]);
        }
        __syncthreads();

        if (iter == 3) {
            for (int i = tid; i < GP; i += 512) {
                float s2 = sh[SIDX(i)];
                g_c[slice*GP + i] = (s2 > 0.0f) ? 1.0f/s2 : 0.0f;
            }
        } else {
#pragma unroll
            for (int u = 0; u < 16; u++) {
                int cc = (u >> 3)*256 + lane*8 + (u & 7);
                float s2 = sh[SIDX(cc)];
                cv[u] = (s2 > 0.0f) ? 1.0f/s2 : 0.0f;
            }
        }
        __syncthreads();
    }
}

// ---------------- write a_dp = diag(r) E diag(c) in [n,i,j,h] layout -----------
__global__ __launch_bounds__(256) void k_adp(float* __restrict__ out) {
    __shared__ __half shE[8][512];
    __shared__ float  csh[8][512];
    __shared__ float  rsh[8];
    int b = blockIdx.x;           // b = n*128 + i
    int n = b >> 7, i = b & 127;
    int tid = threadIdx.x;

    if (tid < 8) rsh[tid] = g_r[(n*8 + tid)*GD + i];
#pragma unroll
    for (int t = 0; t < 2; t++) {
        int f = t*256 + tid;
        int h = f >> 6, qq = f & 63;
        ((uint4*)&shE[h][0])[qq] =
            ((const uint4*)(g_E + ((size_t)(n*8 + h)*GD + i)*GP))[qq];
    }
#pragma unroll
    for (int t = 0; t < 4; t++) {
        int f = t*256 + tid;
        int h = f >> 7, j4 = f & 127;
        ((float4*)&csh[h][0])[j4] =
            ((const float4*)(g_c + (size_t)(n*8 + h)*GP))[j4];
    }
    __syncthreads();

    float* dst = out + (size_t)b * GP * 8;
#pragma unroll
    for (int t = 0; t < 16; t++) {
        int o = t*256 + tid;
        int j = o >> 3, h = o & 7;
        float e = __half2float(shE[h][j]);
        dst[o] = rsh[h] * e * csh[h][j];
    }
}

// ---------------- query embedding (finishes masked sums inline) ----------------
__global__ __launch_bounds__(256) void k_vembed(const float* __restrict__ Wvp,
                                                const float* __restrict__ Wvd,
                                                float* __restrict__ out) {
    __shared__ float sp[DM], sd[DM];
    __shared__ float cnts[2];
    int n = blockIdx.x;
    int tid = threadIdx.x, lane = tid & 31, w = tid >> 5;
    float accp = 0.0f, accd = 0.0f;
#pragma unroll
    for (int s = 0; s < SEG; s++) {
        accp += g_part[((0*NB + n)*SEG + s)*DM + tid];
        accd += g_part[((1*NB + n)*SEG + s)*DM + tid];
    }
    sp[tid] = accp; sd[tid] = accd;
    if (tid < 2) {
        float c = 0.0f;
#pragma unroll
        for (int s = 0; s < SEG; s++) c += g_cpart[(tid*NB + n)*SEG + s];
        cnts[tid] = c;
    }
    __syncthreads();
    float cp = cnts[0], cd = cnts[1];
    for (int o = w; o < DM; o += 8) {
        float acc = 0.0f;
#pragma unroll
        for (int t = 0; t < 8; t++) {
            int k = lane + t*32;
            acc += sp[k]*Wvp[(size_t)o*DM + k] + sd[k]*Wvd[(size_t)o*DM + k];
        }
#pragma unroll
        for (int off = 16; off > 0; off >>= 1) acc += __shfl_xor_sync(0xFFFFFFFFu, acc, off);
        if (lane == 0) {
            out[(size_t)n*512 + o]       = 0.5f * acc / cp;
            out[(size_t)n*512 + 256 + o] = 0.5f * acc / cd;
        }
    }
}

// ---------------- launch ---------------------------------------------------------
extern "C" void kernel_launch(void* const* d_in, const int* in_sizes, int n_in,
                              void* d_out, int out_size) {
    const float* protein = (const float*)d_in[0];
    const float* drug    = (const float*)d_in[1];
    const void*  maskp   = d_in[2];
    const void*  maskd   = d_in[3];
    const float* Wk_p    = (const float*)d_in[5];
    const float* Wv_p    = (const float*)d_in[6];
    const float* Wq_d    = (const float*)d_in[7];
    const float* Wv_d    = (const float*)d_in[9];
    float* out = (float*)d_out;

    size_t adp_elems = (size_t)NB * GD * GP * HN;          // 8388608
    bool write_q   = ((size_t)out_size > adp_elems) || ((size_t)out_size < adp_elems);
    bool write_adp = ((size_t)out_size >= adp_elems);
    size_t adp_off = ((size_t)out_size >= adp_elems + NB*512) ? (size_t)NB*512 : 0;

    k_probe<<<1, 256>>>((const unsigned int*)maskp);
    k_group2<<<NB*GP + NB*GD, 256>>>(protein, drug, maskp, maskd);
    k_msum2<<<dim3(NB, 2, SEG), 256>>>();
    k_proj<<<dim3(64, 2, 2), 256>>>(Wk_p, Wq_d);
    if (write_q) k_vembed<<<NB, 256>>>(Wv_p, Wv_d, out);
    if (write_adp) {
        k_logits<<<dim3(8, NHS), 256>>>();
        k_sink4<<<NHS, 512>>>();
        k_adp<<<NB*GD, 256>>>(out + adp_off);
    }
}

// round 8
// speedup vs baseline: 2.1259x; 1.3443x over previous
#include <cuda_runtime.h>
#include <cuda_fp16.h>
#include <cstdint>

// ---------------- problem constants ----------------
#define NB  16
#define HN  8
#define HDM 32
#define DM  256
#define GP  512
#define GD  128
#define NHS 128          // NB*HN slices
#define SEG 16
// (1/sqrt(32)) * log2(e)
#define EXPSC 0.2550526808750678f

// swizzled smem index: conflict-free for sink4 strip pattern
#define SIDX(c) ((((c) & 31) * 17) + ((c) >> 5))

// ---------------- scratch (static device globals; no runtime alloc) ------------
__device__ float  g_pg[NB*GP*DM];
__device__ float  g_dg[NB*GD*DM];
__device__ float  g_mp[NB*GP];
__device__ float  g_md[NB*GD];
__device__ float  g_part[2*NB*SEG*DM];
__device__ float  g_cpart[2*NB*SEG];
__device__ float  g_kp[NHS*GP*HDM];
__device__ float  g_qd[NHS*GD*HDM];
__device__ __half g_E [NHS*GD*GP];
__device__ float  g_r [NHS*GD];
__device__ float  g_c [NHS*GP];
__device__ int    g_maskmode;

// ---------------- packed f32x2 helpers ------------------------------------------
__device__ __forceinline__ unsigned long long pack2(float x) {
    unsigned long long r;
    asm("mov.b64 %0, {%1, %1};" : "=l"(r) : "r"(__float_as_uint(x)));
    return r;
}
__device__ __forceinline__ void fma2(unsigned long long& d,
                                     unsigned long long a, unsigned long long b) {
    asm("fma.rn.f32x2 %0, %1, %2, %0;" : "+l"(d) : "l"(a), "l"(b));
}
__device__ __forceinline__ float2 unpack2(unsigned long long v) {
    unsigned lo, hi;
    asm("mov.b64 {%0, %1}, %2;" : "=r"(lo), "=r"(hi) : "l"(v));
    return make_float2(__uint_as_float(lo), __uint_as_float(hi));
}

// ---------------- tf32 + mma + ex2 helpers ---------------------------------------
__device__ __forceinline__ uint32_t tf32cvt(float x) {
    uint32_t r;
    asm("cvt.rna.tf32.f32 %0, %1;" : "=r"(r) : "f"(x));
    return r;
}
__device__ __forceinline__ void mma_tf32(float& c0, float& c1, float& c2, float& c3,
                                         uint32_t a0, uint32_t a1, uint32_t a2, uint32_t a3,
                                         uint32_t b0, uint32_t b1) {
    asm volatile(
        "mma.sync.aligned.m16n8k8.row.col.f32.tf32.tf32.f32 "
        "{%0,%1,%2,%3}, {%4,%5,%6,%7}, {%8,%9}, {%0,%1,%2,%3};"
        : "+f"(c0), "+f"(c1), "+f"(c2), "+f"(c3)
        : "r"(a0), "r"(a1), "r"(a2), "r"(a3), "r"(b0), "r"(b1));
}
__device__ __forceinline__ uint32_t ex2_f16x2(uint32_t x) {
    uint32_t r;
    asm("ex2.approx.f16x2 %0, %1;" : "=r"(r) : "r"(x));
    return r;
}

// ---------------- mask dtype probe ------------------------------------------------
__global__ void k_probe(const unsigned int* __restrict__ m) {
    __shared__ int cnt[4];
    int t = threadIdx.x;
    if (t < 4) cnt[t] = 0;
    __syncthreads();
    unsigned w = m[t];
    if (w == 0x3F803F80u || w == 0x3C003C00u) atomicAdd(&cnt[0], 1);
    if (w == 0x3F800000u)                     atomicAdd(&cnt[1], 1);
    if (w > 1u)                               atomicAdd(&cnt[2], 1);
    __syncthreads();
    if (t == 0) {
        int mode;
        if (cnt[0] >= 4)      mode = 3;
        else if (cnt[1] >= 4) mode = 0;
        else if (cnt[2] > 0)  mode = 2;
        else                  mode = 1;
        g_maskmode = mode;
    }
}

__device__ __forceinline__ float mask_at(const void* M, int tok, int mode) {
    switch (mode) {
        case 0:  return ((const float*)M)[tok] != 0.0f ? 1.0f : 0.0f;
        case 1:  return ((const int*)M)[tok]   != 0    ? 1.0f : 0.0f;
        case 2:  return ((const unsigned char*)M)[tok] ? 1.0f : 0.0f;
        default: return ((const unsigned short*)M)[tok] ? 1.0f : 0.0f;
    }
}

// ---------------- grouping --------------------------------------------------------
__global__ void k_group2(const float* __restrict__ P, const float* __restrict__ Dr,
                         const void* __restrict__ MP, const void* __restrict__ MD) {
    int b = blockIdx.x;
    const float* X; const void* M; float* out; float* mout;
    if (b < NB*GP) { X = P;  M = MP; out = g_pg; mout = g_mp; }
    else           { b -= NB*GP; X = Dr; M = MD; out = g_dg; mout = g_md; }
    int d = threadIdx.x;
    const float* src = X + (size_t)b * 4 * DM;
    out[(size_t)b * DM + d] =
        0.25f * (src[d] + src[DM + d] + src[2*DM + d] + src[3*DM + d]);
    if (d == 0) {
        int mode = g_maskmode;
        float m = mask_at(M, 4*b+0, mode) + mask_at(M, 4*b+1, mode)
                + mask_at(M, 4*b+2, mode) + mask_at(M, 4*b+3, mode);
        mout[b] = (m > 0.0f) ? 1.0f : 0.0f;
    }
}

// ---------------- fused launch 1: masked-sum partials + projection GEMM ----------
// blocks [0,512): msum;  [512,768): proj
#define ASTR 137
__global__ __launch_bounds__(256) void k_fuse1(const float* __restrict__ Wkp,
                                               const float* __restrict__ Wqd) {
    if (blockIdx.x < 512) {
        // ---- masked sums, stage 1 ----
        int s = blockIdx.x;
        int n = s & 15, ent = (s >> 4) & 1, seg = s >> 5;
        int d = threadIdx.x;
        const float* X = ent ? g_dg : g_pg;
        const float* m = ent ? g_md : g_mp;
        int G = ent ? GD : GP;
        int chunk = G / SEG;
        int g0 = seg * chunk;
        float a0 = 0.f, a1 = 0.f, a2 = 0.f, a3 = 0.f;
        for (int g = g0; g < g0 + chunk; g += 4) {
            a0 += m[n*G+g+0] * X[((size_t)(n*G+g+0))*DM + d];
            a1 += m[n*G+g+1] * X[((size_t)(n*G+g+1))*DM + d];
            a2 += m[n*G+g+2] * X[((size_t)(n*G+g+2))*DM + d];
            a3 += m[n*G+g+3] * X[((size_t)(n*G+g+3))*DM + d];
        }
        g_part[((ent*NB + n)*SEG + seg)*DM + d] = (a0 + a1) + (a2 + a3);
        if (d == 0) {
            float c = 0.0f;
            for (int g = g0; g < g0 + chunk; g++) c += m[n*G + g];
            g_cpart[(ent*NB + n)*SEG + seg] = c;
        }
        return;
    }
    // ---- projection GEMM: single TF32, CTA 128x128, K-step 32 ----
    int pb = blockIdx.x - 512;            // 0..255
    int bx = pb & 63, by = (pb >> 6) & 1, bz = pb >> 7;
    const float* X; const float* W; float* OUT; int L;
    if (bz == 0) { X = g_pg; W = Wkp; OUT = g_kp; L = GP; }
    else         { if (bx >= 16) return;
                   X = g_dg; W = Wqd; OUT = g_qd; L = GD; }
    __shared__ uint32_t AsH[32*ASTR];
    __shared__ uint32_t BsH[32*ASTR];

    int tid = threadIdx.x;
    int lane = tid & 31, w = tid >> 5;
    int g = lane >> 2, tk = lane & 3;
    int wm = (w & 3) * 32, wn = (w >> 2) * 64;
    int m0 = bx * 128, o0 = by * 128;

    float c[2][8][4];
#pragma unroll
    for (int mi = 0; mi < 2; mi++)
#pragma unroll
        for (int ni = 0; ni < 8; ni++)
#pragma unroll
            for (int r = 0; r < 4; r++) c[mi][ni][r] = 0.0f;

    for (int k0 = 0; k0 < 256; k0 += 32) {
#pragma unroll
        for (int s = 0; s < 4; s++) {
            int f = tid + s*256;              // 0..1023
            int row = f >> 3, c4 = f & 7;     // 8 float4 per 32-col row
            float4 va = *(const float4*)&X[(size_t)(m0+row)*256 + k0 + c4*4];
            AsH[(c4*4+0)*ASTR + row] = tf32cvt(va.x);
            AsH[(c4*4+1)*ASTR + row] = tf32cvt(va.y);
            AsH[(c4*4+2)*ASTR + row] = tf32cvt(va.z);
            AsH[(c4*4+3)*ASTR + row] = tf32cvt(va.w);
            float4 vb = *(const float4*)&W[(size_t)(o0+row)*256 + k0 + c4*4];
            BsH[(c4*4+0)*ASTR + row] = tf32cvt(vb.x);
            BsH[(c4*4+1)*ASTR + row] = tf32cvt(vb.y);
            BsH[(c4*4+2)*ASTR + row] = tf32cvt(vb.z);
            BsH[(c4*4+3)*ASTR + row] = tf32cvt(vb.w);
        }
        __syncthreads();
#pragma unroll
        for (int kh = 0; kh < 4; kh++) {
            int kb = kh*8;
            uint32_t aH[2][4];
#pragma unroll
            for (int mi = 0; mi < 2; mi++) {
                int rb = wm + mi*16 + g;
                aH[mi][0] = AsH[(kb+tk  )*ASTR + rb];
                aH[mi][1] = AsH[(kb+tk  )*ASTR + rb + 8];
                aH[mi][2] = AsH[(kb+tk+4)*ASTR + rb];
                aH[mi][3] = AsH[(kb+tk+4)*ASTR + rb + 8];
            }
            uint32_t bH[8][2];
#pragma unroll
            for (int ni = 0; ni < 8; ni++) {
                int nb = wn + ni*8 + g;
                bH[ni][0] = BsH[(kb+tk  )*ASTR + nb];
                bH[ni][1] = BsH[(kb+tk+4)*ASTR + nb];
            }
#pragma unroll
            for (int mi = 0; mi < 2; mi++)
#pragma unroll
                for (int ni = 0; ni < 8; ni++) {
                    float* cc = c[mi][ni];
                    mma_tf32(cc[0],cc[1],cc[2],cc[3],
                             aH[mi][0],aH[mi][1],aH[mi][2],aH[mi][3],
                             bH[ni][0],bH[ni][1]);
                }
        }
        __syncthreads();
    }

#pragma unroll
    for (int mi = 0; mi < 2; mi++)
#pragma unroll
        for (int ni = 0; ni < 8; ni++) {
            int o = o0 + wn + ni*8 + 2*tk;
            int h = o >> 5, dd = o & 31;
            int m = m0 + wm + mi*16 + g;
            int nb = m / L, gg = m % L;
            float* dst = &OUT[(((size_t)(nb*HN + h))*L + gg)*HDM + dd];
            *(float2*)dst = make_float2(c[mi][ni][0], c[mi][ni][1]);
            int m2 = m + 8;
            int nb2 = m2 / L, gg2 = m2 % L;
            float* dst2 = &OUT[(((size_t)(nb2*HN + h))*L + gg2)*HDM + dd];
            *(float2*)dst2 = make_float2(c[mi][ni][2], c[mi][ni][3]);
        }
}

// ---------------- fused launch 2: logits+exp -> E (fp16)  +  query embedding -----
// blocks [0,1024): logits; [1024,1040): vembed
__global__ __launch_bounds__(256) void k_fuse2(const float* __restrict__ Wvp,
                                               const float* __restrict__ Wvd,
                                               float* __restrict__ qout, int do_q) {
    if (blockIdx.x >= 1024) {
        // ---- query embedding (finishes masked sums) ----
        if (!do_q) return;
        __shared__ float sp[DM], sd[DM];
        __shared__ float cnts[2];
        int n = blockIdx.x - 1024;
        int tid = threadIdx.x, lane = tid & 31, w = tid >> 5;
        float accp = 0.0f, accd = 0.0f;
#pragma unroll
        for (int s = 0; s < SEG; s++) {
            accp += g_part[((0*NB + n)*SEG + s)*DM + tid];
            accd += g_part[((1*NB + n)*SEG + s)*DM + tid];
        }
        sp[tid] = accp; sd[tid] = accd;
        if (tid < 2) {
            float c = 0.0f;
#pragma unroll
            for (int s = 0; s < SEG; s++) c += g_cpart[(tid*NB + n)*SEG + s];
            cnts[tid] = c;
        }
        __syncthreads();
        float cp = cnts[0], cd = cnts[1];
        for (int o = w; o < DM; o += 8) {
            float acc = 0.0f;
#pragma unroll
            for (int t = 0; t < 8; t++) {
                int k = lane + t*32;
                acc += sp[k]*Wvp[(size_t)o*DM + k] + sd[k]*Wvd[(size_t)o*DM + k];
            }
#pragma unroll
            for (int off = 16; off > 0; off >>= 1)
                acc += __shfl_xor_sync(0xFFFFFFFFu, acc, off);
            if (lane == 0) {
                qout[(size_t)n*512 + o]       = 0.5f * acc / cp;
                qout[(size_t)n*512 + 256 + o] = 0.5f * acc / cd;
            }
        }
        return;
    }
    // ---- dp logits GEMM + mask + ex2.f16x2 -> E ----
    __shared__ float Qs[32][132];
    __shared__ float Ks[32][68];
    __shared__ float mr[128], mc[64];
    int tid = threadIdx.x;
    int tx = tid & 15, ty = tid >> 4;
    int j0 = (blockIdx.x & 7) * 64;
    int slice = blockIdx.x >> 3;
    int n = slice >> 3;
    const float* q = g_qd + (size_t)slice * GD * HDM;
    const float* k = g_kp + (size_t)slice * GP * HDM;

#pragma unroll
    for (int s = 0; s < 4; s++) {
        int f = tid + s*256;
        int row = f >> 3, c4 = f & 7;
        float4 v = *(const float4*)&q[(size_t)row*HDM + c4*4];
        Qs[c4*4+0][row] = v.x; Qs[c4*4+1][row] = v.y;
        Qs[c4*4+2][row] = v.z; Qs[c4*4+3][row] = v.w;
    }
#pragma unroll
    for (int s = 0; s < 2; s++) {
        int f = tid + s*256;
        int row = f >> 3, c4 = f & 7;
        float4 v = *(const float4*)&k[(size_t)(j0+row)*HDM + c4*4];
        Ks[c4*4+0][row] = v.x; Ks[c4*4+1][row] = v.y;
        Ks[c4*4+2][row] = v.z; Ks[c4*4+3][row] = v.w;
    }
    if (tid < 128) mr[tid] = g_md[n*GD + tid];
    if (tid < 64)  mc[tid] = g_mp[n*GP + j0 + tid];
    __syncthreads();

    unsigned long long acc2[4][4];
#pragma unroll
    for (int u = 0; u < 4; u++)
#pragma unroll
        for (int v = 0; v < 4; v++) acc2[u][v] = 0ULL;
#pragma unroll
    for (int kk = 0; kk < 32; kk++) {
        ulonglong2 ap01 = *(const ulonglong2*)&Qs[kk][ty*8];
        ulonglong2 ap23 = *(const ulonglong2*)&Qs[kk][ty*8 + 4];
        unsigned long long ap[4] = {ap01.x, ap01.y, ap23.x, ap23.y};
        float4 b = *(const float4*)&Ks[kk][tx*4];
        unsigned long long bb[4] = {pack2(b.x), pack2(b.y), pack2(b.z), pack2(b.w)};
#pragma unroll
        for (int u = 0; u < 4; u++)
#pragma unroll
            for (int v = 0; v < 4; v++) fma2(acc2[u][v], ap[u], bb[v]);
    }
    float acc[8][4];
#pragma unroll
    for (int up = 0; up < 4; up++)
#pragma unroll
        for (int v = 0; v < 4; v++) {
            float2 p = unpack2(acc2[up][v]);
            acc[up*2][v] = p.x; acc[up*2+1][v] = p.y;
        }
#pragma unroll
    for (int u = 0; u < 8; u++) {
        int i = ty*8 + u;
        float rm = mr[i];
        __half2 xa = __floats2half2_rn(acc[u][0]*EXPSC, acc[u][1]*EXPSC);
        __half2 xb = __floats2half2_rn(acc[u][2]*EXPSC, acc[u][3]*EXPSC);
        uint32_t ea = ex2_f16x2(*(uint32_t*)&xa);
        uint32_t eb = ex2_f16x2(*(uint32_t*)&xb);
        __half2 ma = __floats2half2_rn(rm*mc[tx*4+0], rm*mc[tx*4+1]);
        __half2 mb = __floats2half2_rn(rm*mc[tx*4+2], rm*mc[tx*4+3]);
        __half2 ha = __hmul2(*(__half2*)&ea, ma);
        __half2 hb = __hmul2(*(__half2*)&eb, mb);
        __half2* dst = (__half2*)&g_E[(size_t)slice*GD*GP + (size_t)i*GP + j0 + tx*4];
        dst[0] = ha; dst[1] = hb;
    }
}

// ---------------- fused 4-iteration Sinkhorn (strip reduction, no atomics) -------
// One block per slice: 128 rows x 512 cols. 512 threads = 16 warps; warp strips.
__global__ __launch_bounds__(512) void k_sink4() {
    int slice = blockIdx.x;
    int tid = threadIdx.x, lane = tid & 31, w = tid >> 5;
    const __half* Es = g_E + (size_t)slice * GD * GP;
    __shared__ float strip[16*544];

    float cv[16];
#pragma unroll
    for (int u = 0; u < 16; u++) cv[u] = 1.0f;

    for (int iter = 0; iter < 4; iter++) {
        float colacc[16];
#pragma unroll
        for (int u = 0; u < 16; u++) colacc[u] = 0.0f;

#pragma unroll
        for (int ridx = 0; ridx < 8; ridx++) {
            int i = w + ridx*16;
            const uint4* rp = (const uint4*)(Es + (size_t)i * GP);
            float ev[16];
            float s = 0.0f;
#pragma unroll
            for (int ch = 0; ch < 2; ch++) {
                uint4 raw = rp[ch*32 + lane];
                float2 f0 = __half22float2(*(__half2*)&raw.x);
                float2 f1 = __half22float2(*(__half2*)&raw.y);
                float2 f2 = __half22float2(*(__half2*)&raw.z);
                float2 f3 = __half22float2(*(__half2*)&raw.w);
                ev[ch*8+0] = f0.x; ev[ch*8+1] = f0.y;
                ev[ch*8+2] = f1.x; ev[ch*8+3] = f1.y;
                ev[ch*8+4] = f2.x; ev[ch*8+5] = f2.y;
                ev[ch*8+6] = f3.x; ev[ch*8+7] = f3.y;
            }
#pragma unroll
            for (int u = 0; u < 16; u++) s += ev[u] * cv[u];
#pragma unroll
            for (int off = 16; off > 0; off >>= 1)
                s += __shfl_xor_sync(0xFFFFFFFFu, s, off);
            float r = (s > 0.0f) ? 1.0f/s : 0.0f;
            if (iter == 3 && lane == 0) g_r[slice*GD + i] = r;
#pragma unroll
            for (int u = 0; u < 16; u++) colacc[u] += r * ev[u];
        }
        // write per-warp column partials to the warp's strip (conflict-free)
#pragma unroll
        for (int u = 0; u < 16; u++) {
            int cc = (u >> 3)*256 + lane*8 + (u & 7);
            strip[w*544 + SIDX(cc)] = colacc[u];
        }
        __syncthreads();
        // cross-strip reduction: thread tid handles column tid
        {
            int cc = tid;        // 0..511
            float s2 = 0.0f;
#pragma unroll
            for (int ww = 0; ww < 16; ww++) s2 += strip[ww*544 + SIDX(cc)];
            float rec = (s2 > 0.0f) ? 1.0f/s2 : 0.0f;
            if (iter == 3) g_c[slice*GP + cc] = rec;
            else           strip[SIDX(cc)] = rec;   // row 0 reused as broadcast
        }
        __syncthreads();
        if (iter < 3) {
#pragma unroll
            for (int u = 0; u < 16; u++) {
                int cc = (u >> 3)*256 + lane*8 + (u & 7);
                cv[u] = strip[SIDX(cc)];
            }
            __syncthreads();   // protect row 0 before next iter's strip writes
        }
    }
}

// ---------------- write a_dp = diag(r) E diag(c) in [n,i,j,h] layout --------------
__global__ __launch_bounds__(256) void k_adp(float* __restrict__ out) {
    __shared__ __half shE[8][512];
    __shared__ float  csh[8][512];
    __shared__ float  rsh[8];
    int b = blockIdx.x;           // b = n*128 + i
    int n = b >> 7, i = b & 127;
    int tid = threadIdx.x;

    if (tid < 8) rsh[tid] = g_r[(n*8 + tid)*GD + i];
#pragma unroll
    for (int t = 0; t < 2; t++) {
        int f = t*256 + tid;
        int h = f >> 6, qq = f & 63;
        ((uint4*)&shE[h][0])[qq] =
            ((const uint4*)(g_E + ((size_t)(n*8 + h)*GD + i)*GP))[qq];
    }
#pragma unroll
    for (int t = 0; t < 4; t++) {
        int f = t*256 + tid;
        int h = f >> 7, j4 = f & 127;
        ((float4*)&csh[h][0])[j4] =
            ((const float4*)(g_c + (size_t)(n*8 + h)*GP))[j4];
    }
    __syncthreads();

    float* dst = out + (size_t)b * GP * 8;
#pragma unroll
    for (int t = 0; t < 16; t++) {
        int o = t*256 + tid;
        int j = o >> 3, h = o & 7;
        float e = __half2float(shE[h][j]);
        dst[o] = rsh[h] * e * csh[h][j];
    }
}

// ---------------- launch -----------------------------------------------------------
extern "C" void kernel_launch(void* const* d_in, const int* in_sizes, int n_in,
                              void* d_out, int out_size) {
    const float* protein = (const float*)d_in[0];
    const float* drug    = (const float*)d_in[1];
    const void*  maskp   = d_in[2];
    const void*  maskd   = d_in[3];
    const float* Wk_p    = (const float*)d_in[5];
    const float* Wv_p    = (const float*)d_in[6];
    const float* Wq_d    = (const float*)d_in[7];
    const float* Wv_d    = (const float*)d_in[9];
    float* out = (float*)d_out;

    size_t adp_elems = (size_t)NB * GD * GP * HN;          // 8388608
    int  write_q   = (((size_t)out_size > adp_elems) || ((size_t)out_size < adp_elems)) ? 1 : 0;
    bool write_adp = ((size_t)out_size >= adp_elems);
    size_t adp_off = ((size_t)out_size >= adp_elems + NB*512) ? (size_t)NB*512 : 0;

    k_probe<<<1, 256>>>((const unsigned int*)maskp);
    k_group2<<<NB*GP + NB*GD, 256>>>(protein, drug, maskp, maskd);
    k_fuse1<<<768, 256>>>(Wk_p, Wq_d);
    k_fuse2<<<1040, 256>>>(Wv_p, Wv_d, out, write_q);
    if (write_adp) {
        k_sink4<<<NHS, 512>>>();
        k_adp<<<NB*GD, 256>>>(out + adp_off);
    }
}

// round 9
// speedup vs baseline: 2.1323x; 1.0030x over previous
#include <cuda_runtime.h>
#include <cuda_fp16.h>
#include <cstdint>

// ---------------- problem constants ----------------
#define NB  16
#define HN  8
#define HDM 32
#define DM  256
#define GP  512
#define GD  128
#define NHS 128          // NB*HN slices
#define SEG 16
// (1/sqrt(32)) * log2(e)
#define EXPSC 0.2550526808750678f

// swizzled smem index: conflict-free for sink4 strip pattern
#define SIDX(c) ((((c) & 31) * 17) + ((c) >> 5))

// ---------------- scratch (static device globals; no runtime alloc) ------------
__device__ float  g_pg[NB*GP*DM];
__device__ float  g_dg[NB*GD*DM];
__device__ float  g_mp[NB*GP];
__device__ float  g_md[NB*GD];
__device__ float  g_part[2*NB*SEG*DM];
__device__ float  g_cpart[2*NB*SEG];
__device__ float  g_kp[NHS*GP*HDM];
__device__ float  g_qd[NHS*GD*HDM];
__device__ __half g_E [NHS*GD*GP];
__device__ float  g_r [NHS*GD];
__device__ float  g_c [NHS*GP];
__device__ int    g_maskmode;

// ---------------- tf32 + mma + ex2 helpers ---------------------------------------
__device__ __forceinline__ uint32_t tf32cvt(float x) {
    uint32_t r;
    asm("cvt.rna.tf32.f32 %0, %1;" : "=r"(r) : "f"(x));
    return r;
}
__device__ __forceinline__ void mma_tf32(float& c0, float& c1, float& c2, float& c3,
                                         uint32_t a0, uint32_t a1, uint32_t a2, uint32_t a3,
                                         uint32_t b0, uint32_t b1) {
    asm volatile(
        "mma.sync.aligned.m16n8k8.row.col.f32.tf32.tf32.f32 "
        "{%0,%1,%2,%3}, {%4,%5,%6,%7}, {%8,%9}, {%0,%1,%2,%3};"
        : "+f"(c0), "+f"(c1), "+f"(c2), "+f"(c3)
        : "r"(a0), "r"(a1), "r"(a2), "r"(a3), "r"(b0), "r"(b1));
}
__device__ __forceinline__ uint32_t ex2_f16x2(uint32_t x) {
    uint32_t r;
    asm("ex2.approx.f16x2 %0, %1;" : "=r"(r) : "r"(x));
    return r;
}

// ---------------- mask dtype probe ------------------------------------------------
__global__ void k_probe(const unsigned int* __restrict__ m) {
    __shared__ int cnt[4];
    int t = threadIdx.x;
    if (t < 4) cnt[t] = 0;
    __syncthreads();
    unsigned w = m[t];
    if (w == 0x3F803F80u || w == 0x3C003C00u) atomicAdd(&cnt[0], 1);
    if (w == 0x3F800000u)                     atomicAdd(&cnt[1], 1);
    if (w > 1u)                               atomicAdd(&cnt[2], 1);
    __syncthreads();
    if (t == 0) {
        int mode;
        if (cnt[0] >= 4)      mode = 3;
        else if (cnt[1] >= 4) mode = 0;
        else if (cnt[2] > 0)  mode = 2;
        else                  mode = 1;
        g_maskmode = mode;
    }
}

__device__ __forceinline__ float mask_at(const void* M, int tok, int mode) {
    switch (mode) {
        case 0:  return ((const float*)M)[tok] != 0.0f ? 1.0f : 0.0f;
        case 1:  return ((const int*)M)[tok]   != 0    ? 1.0f : 0.0f;
        case 2:  return ((const unsigned char*)M)[tok] ? 1.0f : 0.0f;
        default: return ((const unsigned short*)M)[tok] ? 1.0f : 0.0f;
    }
}

// ---------------- grouping --------------------------------------------------------
__global__ void k_group2(const float* __restrict__ P, const float* __restrict__ Dr,
                         const void* __restrict__ MP, const void* __restrict__ MD) {
    int b = blockIdx.x;
    const float* X; const void* M; float* out; float* mout;
    if (b < NB*GP) { X = P;  M = MP; out = g_pg; mout = g_mp; }
    else           { b -= NB*GP; X = Dr; M = MD; out = g_dg; mout = g_md; }
    int d = threadIdx.x;
    const float* src = X + (size_t)b * 4 * DM;
    out[(size_t)b * DM + d] =
        0.25f * (src[d] + src[DM + d] + src[2*DM + d] + src[3*DM + d]);
    if (d == 0) {
        int mode = g_maskmode;
        float m = mask_at(M, 4*b+0, mode) + mask_at(M, 4*b+1, mode)
                + mask_at(M, 4*b+2, mode) + mask_at(M, 4*b+3, mode);
        mout[b] = (m > 0.0f) ? 1.0f : 0.0f;
    }
}

// ---------------- fused launch 1: masked-sum partials + projection GEMM ----------
// blocks [0,512): msum;  [512,768): proj
#define ASTR 137
__global__ __launch_bounds__(256) void k_fuse1(const float* __restrict__ Wkp,
                                               const float* __restrict__ Wqd) {
    if (blockIdx.x < 512) {
        int s = blockIdx.x;
        int n = s & 15, ent = (s >> 4) & 1, seg = s >> 5;
        int d = threadIdx.x;
        const float* X = ent ? g_dg : g_pg;
        const float* m = ent ? g_md : g_mp;
        int G = ent ? GD : GP;
        int chunk = G / SEG;
        int g0 = seg * chunk;
        float a0 = 0.f, a1 = 0.f, a2 = 0.f, a3 = 0.f;
        for (int g = g0; g < g0 + chunk; g += 4) {
            a0 += m[n*G+g+0] * X[((size_t)(n*G+g+0))*DM + d];
            a1 += m[n*G+g+1] * X[((size_t)(n*G+g+1))*DM + d];
            a2 += m[n*G+g+2] * X[((size_t)(n*G+g+2))*DM + d];
            a3 += m[n*G+g+3] * X[((size_t)(n*G+g+3))*DM + d];
        }
        g_part[((ent*NB + n)*SEG + seg)*DM + d] = (a0 + a1) + (a2 + a3);
        if (d == 0) {
            float c = 0.0f;
            for (int g = g0; g < g0 + chunk; g++) c += m[n*G + g];
            g_cpart[(ent*NB + n)*SEG + seg] = c;
        }
        return;
    }
    // ---- projection GEMM: single TF32, CTA 128x128, K-step 32 ----
    int pb = blockIdx.x - 512;
    int bx = pb & 63, by = (pb >> 6) & 1, bz = pb >> 7;
    const float* X; const float* W; float* OUT; int L;
    if (bz == 0) { X = g_pg; W = Wkp; OUT = g_kp; L = GP; }
    else         { if (bx >= 16) return;
                   X = g_dg; W = Wqd; OUT = g_qd; L = GD; }
    __shared__ uint32_t AsH[32*ASTR];
    __shared__ uint32_t BsH[32*ASTR];

    int tid = threadIdx.x;
    int lane = tid & 31, w = tid >> 5;
    int g = lane >> 2, tk = lane & 3;
    int wm = (w & 3) * 32, wn = (w >> 2) * 64;
    int m0 = bx * 128, o0 = by * 128;

    float c[2][8][4];
#pragma unroll
    for (int mi = 0; mi < 2; mi++)
#pragma unroll
        for (int ni = 0; ni < 8; ni++)
#pragma unroll
            for (int r = 0; r < 4; r++) c[mi][ni][r] = 0.0f;

    for (int k0 = 0; k0 < 256; k0 += 32) {
#pragma unroll
        for (int s = 0; s < 4; s++) {
            int f = tid + s*256;
            int row = f >> 3, c4 = f & 7;
            float4 va = *(const float4*)&X[(size_t)(m0+row)*256 + k0 + c4*4];
            AsH[(c4*4+0)*ASTR + row] = tf32cvt(va.x);
            AsH[(c4*4+1)*ASTR + row] = tf32cvt(va.y);
            AsH[(c4*4+2)*ASTR + row] = tf32cvt(va.z);
            AsH[(c4*4+3)*ASTR + row] = tf32cvt(va.w);
            float4 vb = *(const float4*)&W[(size_t)(o0+row)*256 + k0 + c4*4];
            BsH[(c4*4+0)*ASTR + row] = tf32cvt(vb.x);
            BsH[(c4*4+1)*ASTR + row] = tf32cvt(vb.y);
            BsH[(c4*4+2)*ASTR + row] = tf32cvt(vb.z);
            BsH[(c4*4+3)*ASTR + row] = tf32cvt(vb.w);
        }
        __syncthreads();
#pragma unroll
        for (int kh = 0; kh < 4; kh++) {
            int kb = kh*8;
            uint32_t aH[2][4];
#pragma unroll
            for (int mi = 0; mi < 2; mi++) {
                int rb = wm + mi*16 + g;
                aH[mi][0] = AsH[(kb+tk  )*ASTR + rb];
                aH[mi][1] = AsH[(kb+tk  )*ASTR + rb + 8];
                aH[mi][2] = AsH[(kb+tk+4)*ASTR + rb];
                aH[mi][3] = AsH[(kb+tk+4)*ASTR + rb + 8];
            }
            uint32_t bH[8][2];
#pragma unroll
            for (int ni = 0; ni < 8; ni++) {
                int nb = wn + ni*8 + g;
                bH[ni][0] = BsH[(kb+tk  )*ASTR + nb];
                bH[ni][1] = BsH[(kb+tk+4)*ASTR + nb];
            }
#pragma unroll
            for (int mi = 0; mi < 2; mi++)
#pragma unroll
                for (int ni = 0; ni < 8; ni++) {
                    float* cc = c[mi][ni];
                    mma_tf32(cc[0],cc[1],cc[2],cc[3],
                             aH[mi][0],aH[mi][1],aH[mi][2],aH[mi][3],
                             bH[ni][0],bH[ni][1]);
                }
        }
        __syncthreads();
    }

#pragma unroll
    for (int mi = 0; mi < 2; mi++)
#pragma unroll
        for (int ni = 0; ni < 8; ni++) {
            int o = o0 + wn + ni*8 + 2*tk;
            int h = o >> 5, dd = o & 31;
            int m = m0 + wm + mi*16 + g;
            int nb = m / L, gg = m % L;
            float* dst = &OUT[(((size_t)(nb*HN + h))*L + gg)*HDM + dd];
            *(float2*)dst = make_float2(c[mi][ni][0], c[mi][ni][1]);
            int m2 = m + 8;
            int nb2 = m2 / L, gg2 = m2 % L;
            float* dst2 = &OUT[(((size_t)(nb2*HN + h))*L + gg2)*HDM + dd];
            *(float2*)dst2 = make_float2(c[mi][ni][2], c[mi][ni][3]);
        }
}

// ---------------- fused launch 2: TF32-MMA logits + exp -> E  +  query embedding --
// blocks [0,1024): logits (slice = b>>3, j-tile = b&7); [1024,1040): vembed
#define QSTR 137
#define KSTR 72
__global__ __launch_bounds__(256) void k_fuse2(const float* __restrict__ Wvp,
                                               const float* __restrict__ Wvd,
                                               float* __restrict__ qout, int do_q) {
    if (blockIdx.x >= 1024) {
        if (!do_q) return;
        __shared__ float sp[DM], sd[DM];
        __shared__ float cnts[2];
        int n = blockIdx.x - 1024;
        int tid = threadIdx.x, lane = tid & 31, w = tid >> 5;
        float accp = 0.0f, accd = 0.0f;
#pragma unroll
        for (int s = 0; s < SEG; s++) {
            accp += g_part[((0*NB + n)*SEG + s)*DM + tid];
            accd += g_part[((1*NB + n)*SEG + s)*DM + tid];
        }
        sp[tid] = accp; sd[tid] = accd;
        if (tid < 2) {
            float c = 0.0f;
#pragma unroll
            for (int s = 0; s < SEG; s++) c += g_cpart[(tid*NB + n)*SEG + s];
            cnts[tid] = c;
        }
        __syncthreads();
        float cp = cnts[0], cd = cnts[1];
        for (int o = w; o < DM; o += 8) {
            float acc = 0.0f;
#pragma unroll
            for (int t = 0; t < 8; t++) {
                int k = lane + t*32;
                acc += sp[k]*Wvp[(size_t)o*DM + k] + sd[k]*Wvd[(size_t)o*DM + k];
            }
#pragma unroll
            for (int off = 16; off > 0; off >>= 1)
                acc += __shfl_xor_sync(0xFFFFFFFFu, acc, off);
            if (lane == 0) {
                qout[(size_t)n*512 + o]       = 0.5f * acc / cp;
                qout[(size_t)n*512 + 256 + o] = 0.5f * acc / cd;
            }
        }
        return;
    }
    // ---- TF32 tensor-core logits: tile 128(i) x 64(j), K=32, one fill ----
    __shared__ uint32_t Qs[32*QSTR];
    __shared__ uint32_t Ks[32*KSTR];
    __shared__ float mr[128], mc[64];
    int tid = threadIdx.x;
    int lane = tid & 31, w = tid >> 5;
    int g = lane >> 2, tk = lane & 3;
    int wm = (w & 3) * 32, wn = (w >> 2) * 32;    // 8 warps: 4(M) x 2(N), warp 32x32
    int j0 = (blockIdx.x & 7) * 64;
    int slice = blockIdx.x >> 3;
    int n = slice >> 3;
    const float* q = g_qd + (size_t)slice * GD * HDM;
    const float* k = g_kp + (size_t)slice * GP * HDM;

#pragma unroll
    for (int s = 0; s < 4; s++) {                 // Q: 128x32 = 1024 float4
        int f = tid + s*256;
        int row = f >> 3, c4 = f & 7;
        float4 v = *(const float4*)&q[(size_t)row*HDM + c4*4];
        Qs[(c4*4+0)*QSTR + row] = tf32cvt(v.x);
        Qs[(c4*4+1)*QSTR + row] = tf32cvt(v.y);
        Qs[(c4*4+2)*QSTR + row] = tf32cvt(v.z);
        Qs[(c4*4+3)*QSTR + row] = tf32cvt(v.w);
    }
#pragma unroll
    for (int s = 0; s < 2; s++) {                 // K: 64x32 = 512 float4
        int f = tid + s*256;
        int row = f >> 3, c4 = f & 7;
        float4 v = *(const float4*)&k[(size_t)(j0+row)*HDM + c4*4];
        Ks[(c4*4+0)*KSTR + row] = tf32cvt(v.x);
        Ks[(c4*4+1)*KSTR + row] = tf32cvt(v.y);
        Ks[(c4*4+2)*KSTR + row] = tf32cvt(v.z);
        Ks[(c4*4+3)*KSTR + row] = tf32cvt(v.w);
    }
    if (tid < 128) mr[tid] = g_md[n*GD + tid];
    if (tid < 64)  mc[tid] = g_mp[n*GP + j0 + tid];
    __syncthreads();

    float c[2][4][4];
#pragma unroll
    for (int mi = 0; mi < 2; mi++)
#pragma unroll
        for (int ni = 0; ni < 4; ni++)
#pragma unroll
            for (int r = 0; r < 4; r++) c[mi][ni][r] = 0.0f;

#pragma unroll
    for (int kh = 0; kh < 4; kh++) {
        int kb = kh*8;
        uint32_t aH[2][4];
#pragma unroll
        for (int mi = 0; mi < 2; mi++) {
            int rb = wm + mi*16 + g;
            aH[mi][0] = Qs[(kb+tk  )*QSTR + rb];
            aH[mi][1] = Qs[(kb+tk  )*QSTR + rb + 8];
            aH[mi][2] = Qs[(kb+tk+4)*QSTR + rb];
            aH[mi][3] = Qs[(kb+tk+4)*QSTR + rb + 8];
        }
        uint32_t bH[4][2];
#pragma unroll
        for (int ni = 0; ni < 4; ni++) {
            int nb = wn + ni*8 + g;
            bH[ni][0] = Ks[(kb+tk  )*KSTR + nb];
            bH[ni][1] = Ks[(kb+tk+4)*KSTR + nb];
        }
#pragma unroll
        for (int mi = 0; mi < 2; mi++)
#pragma unroll
            for (int ni = 0; ni < 4; ni++) {
                float* cc = c[mi][ni];
                mma_tf32(cc[0],cc[1],cc[2],cc[3],
                         aH[mi][0],aH[mi][1],aH[mi][2],aH[mi][3],
                         bH[ni][0],bH[ni][1]);
            }
    }

    // epilogue: mask + ex2.f16x2 + fp16 store (cols o, o+1 contiguous)
#pragma unroll
    for (int mi = 0; mi < 2; mi++) {
        int row1 = wm + mi*16 + g;
        int row2 = row1 + 8;
        float rm1 = mr[row1], rm2 = mr[row2];
#pragma unroll
        for (int ni = 0; ni < 4; ni++) {
            int o = wn + ni*8 + 2*tk;
            float m0v = mc[o], m1v = mc[o+1];
            float* cc = c[mi][ni];
            __half2 xa = __floats2half2_rn(cc[0]*EXPSC, cc[1]*EXPSC);
            uint32_t ea = ex2_f16x2(*(uint32_t*)&xa);
            __half2 ma = __floats2half2_rn(rm1*m0v, rm1*m1v);
            __half2 ha = __hmul2(*(__half2*)&ea, ma);
            *(__half2*)&g_E[(size_t)slice*GD*GP + (size_t)row1*GP + j0 + o] = ha;
            __half2 xb = __floats2half2_rn(cc[2]*EXPSC, cc[3]*EXPSC);
            uint32_t eb = ex2_f16x2(*(uint32_t*)&xb);
            __half2 mb = __floats2half2_rn(rm2*m0v, rm2*m1v);
            __half2 hb = __hmul2(*(__half2*)&eb, mb);
            *(__half2*)&g_E[(size_t)slice*GD*GP + (size_t)row2*GP + j0 + o] = hb;
        }
    }
}

// ---------------- fused 4-iteration Sinkhorn (strip reduction, no atomics) -------
__global__ __launch_bounds__(512) void k_sink4() {
    int slice = blockIdx.x;
    int tid = threadIdx.x, lane = tid & 31, w = tid >> 5;
    const __half* Es = g_E + (size_t)slice * GD * GP;
    __shared__ float strip[16*544];

    float cv[16];
#pragma unroll
    for (int u = 0; u < 16; u++) cv[u] = 1.0f;

    for (int iter = 0; iter < 4; iter++) {
        float colacc[16];
#pragma unroll
        for (int u = 0; u < 16; u++) colacc[u] = 0.0f;

#pragma unroll
        for (int ridx = 0; ridx < 8; ridx++) {
            int i = w + ridx*16;
            const uint4* rp = (const uint4*)(Es + (size_t)i * GP);
            float ev[16];
            float s = 0.0f;
#pragma unroll
            for (int ch = 0; ch < 2; ch++) {
                uint4 raw = rp[ch*32 + lane];
                float2 f0 = __half22float2(*(__half2*)&raw.x);
                float2 f1 = __half22float2(*(__half2*)&raw.y);
                float2 f2 = __half22float2(*(__half2*)&raw.z);
                float2 f3 = __half22float2(*(__half2*)&raw.w);
                ev[ch*8+0] = f0.x; ev[ch*8+1] = f0.y;
                ev[ch*8+2] = f1.x; ev[ch*8+3] = f1.y;
                ev[ch*8+4] = f2.x; ev[ch*8+5] = f2.y;
                ev[ch*8+6] = f3.x; ev[ch*8+7] = f3.y;
            }
#pragma unroll
            for (int u = 0; u < 16; u++) s += ev[u] * cv[u];
#pragma unroll
            for (int off = 16; off > 0; off >>= 1)
                s += __shfl_xor_sync(0xFFFFFFFFu, s, off);
            float r = (s > 0.0f) ? 1.0f/s : 0.0f;
            if (iter == 3 && lane == 0) g_r[slice*GD + i] = r;
#pragma unroll
            for (int u = 0; u < 16; u++) colacc[u] += r * ev[u];
        }
#pragma unroll
        for (int u = 0; u < 16; u++) {
            int cc = (u >> 3)*256 + lane*8 + (u & 7);
            strip[w*544 + SIDX(cc)] = colacc[u];
        }
        __syncthreads();
        {
            int cc = tid;
            float s2 = 0.0f;
#pragma unroll
            for (int ww = 0; ww < 16; ww++) s2 += strip[ww*544 + SIDX(cc)];
            float rec = (s2 > 0.0f) ? 1.0f/s2 : 0.0f;
            if (iter == 3) g_c[slice*GP + cc] = rec;
            else           strip[SIDX(cc)] = rec;
        }
        __syncthreads();
        if (iter < 3) {
#pragma unroll
            for (int u = 0; u < 16; u++) {
                int cc = (u >> 3)*256 + lane*8 + (u & 7);
                cv[u] = strip[SIDX(cc)];
            }
            __syncthreads();
        }
    }
}

// ---------------- write a_dp = diag(r) E diag(c) in [n,i,j,h] layout --------------
__global__ __launch_bounds__(256) void k_adp(float* __restrict__ out) {
    __shared__ __half shE[8][512];
    __shared__ float  csh[8][512];
    __shared__ float  rsh[8];
    int b = blockIdx.x;
    int n = b >> 7, i = b & 127;
    int tid = threadIdx.x;

    if (tid < 8) rsh[tid] = g_r[(n*8 + tid)*GD + i];
#pragma unroll
    for (int t = 0; t < 2; t++) {
        int f = t*256 + tid;
        int h = f >> 6, qq = f & 63;
        ((uint4*)&shE[h][0])[qq] =
            ((const uint4*)(g_E + ((size_t)(n*8 + h)*GD + i)*GP))[qq];
    }
#pragma unroll
    for (int t = 0; t < 4; t++) {
        int f = t*256 + tid;
        int h = f >> 7, j4 = f & 127;
        ((float4*)&csh[h][0])[j4] =
            ((const float4*)(g_c + (size_t)(n*8 + h)*GP))[j4];
    }
    __syncthreads();

    float* dst = out + (size_t)b * GP * 8;
#pragma unroll
    for (int t = 0; t < 16; t++) {
        int o = t*256 + tid;
        int j = o >> 3, h = o & 7;
        float e = __half2float(shE[h][j]);
        dst[o] = rsh[h] * e * csh[h][j];
    }
}

// ---------------- launch -----------------------------------------------------------
extern "C" void kernel_launch(void* const* d_in, const int* in_sizes, int n_in,
                              void* d_out, int out_size) {
    const float* protein = (const float*)d_in[0];
    const float* drug    = (const float*)d_in[1];
    const void*  maskp   = d_in[2];
    const void*  maskd   = d_in[3];
    const float* Wk_p    = (const float*)d_in[5];
    const float* Wv_p    = (const float*)d_in[6];
    const float* Wq_d    = (const float*)d_in[7];
    const float* Wv_d    = (const float*)d_in[9];
    float* out = (float*)d_out;

    size_t adp_elems = (size_t)NB * GD * GP * HN;
    int  write_q   = (((size_t)out_size > adp_elems) || ((size_t)out_size < adp_elems)) ? 1 : 0;
    bool write_adp = ((size_t)out_size >= adp_elems);
    size_t adp_off = ((size_t)out_size >= adp_elems + NB*512) ? (size_t)NB*512 : 0;

    k_probe<<<1, 256>>>((const unsigned int*)maskp);
    k_group2<<<NB*GP + NB*GD, 256>>>(protein, drug, maskp, maskd);
    k_fuse1<<<768, 256>>>(Wk_p, Wq_d);
    k_fuse2<<<1040, 256>>>(Wv_p, Wv_d, out, write_q);
    if (write_adp) {
        k_sink4<<<NHS, 512>>>();
        k_adp<<<NB*GD, 256>>>(out + adp_off);
    }
}

// round 10
// speedup vs baseline: 2.7412x; 1.2856x over previous
#include <cuda_runtime.h>
#include <cuda_fp16.h>
#include <cstdint>

// ---------------- problem constants ----------------
#define NB  16
#define HN  8
#define HDM 32
#define DM  256
#define GP  512
#define GD  128
#define NHS 128          // NB*HN slices
#define SEG 16
// (1/sqrt(32)) * log2(e)
#define EXPSC 0.2550526808750678f

// swizzled smem index: conflict-free for sink strip pattern
#define SIDX(c) ((((c) & 31) * 17) + ((c) >> 5))

// mega-kernel shared memory layout (bytes)
#define ESTR   520                       // halfs per E row (1040B: +4 banks/row)
#define SM_E   0                         // 128*520*2 = 133120
#define SM_QK  133120                    // Qs 32*137*4 =17536 ; Ks +17536 (strips alias)
#define SM_MR  168192                    // float[128]
#define SM_MC  168704                    // float[512]
#define SM_TOT 170752

// ---------------- scratch (static device globals; no runtime alloc) ------------
__device__ float  g_pg[NB*GP*DM];
__device__ float  g_dg[NB*GD*DM];
__device__ float  g_mp[NB*GP];
__device__ float  g_md[NB*GD];
__device__ float  g_part[2*NB*SEG*DM];
__device__ float  g_cpart[2*NB*SEG];
__device__ float  g_kp[NHS*GP*HDM];
__device__ float  g_qd[NHS*GD*HDM];
__device__ __half g_E [NHS*GD*GP];
__device__ float  g_r [NHS*GD];
__device__ float  g_c [NHS*GP];
__device__ int    g_maskmode;

// ---------------- tf32 + mma + ex2 helpers ---------------------------------------
__device__ __forceinline__ uint32_t tf32cvt(float x) {
    uint32_t r;
    asm("cvt.rna.tf32.f32 %0, %1;" : "=r"(r) : "f"(x));
    return r;
}
__device__ __forceinline__ void mma_tf32(float& c0, float& c1, float& c2, float& c3,
                                         uint32_t a0, uint32_t a1, uint32_t a2, uint32_t a3,
                                         uint32_t b0, uint32_t b1) {
    asm volatile(
        "mma.sync.aligned.m16n8k8.row.col.f32.tf32.tf32.f32 "
        "{%0,%1,%2,%3}, {%4,%5,%6,%7}, {%8,%9}, {%0,%1,%2,%3};"
        : "+f"(c0), "+f"(c1), "+f"(c2), "+f"(c3)
        : "r"(a0), "r"(a1), "r"(a2), "r"(a3), "r"(b0), "r"(b1));
}
__device__ __forceinline__ uint32_t ex2_f16x2(uint32_t x) {
    uint32_t r;
    asm("ex2.approx.f16x2 %0, %1;" : "=r"(r) : "r"(x));
    return r;
}

// ---------------- mask dtype probe ------------------------------------------------
__global__ void k_probe(const unsigned int* __restrict__ m) {
    __shared__ int cnt[4];
    int t = threadIdx.x;
    if (t < 4) cnt[t] = 0;
    __syncthreads();
    unsigned w = m[t];
    if (w == 0x3F803F80u || w == 0x3C003C00u) atomicAdd(&cnt[0], 1);
    if (w == 0x3F800000u)                     atomicAdd(&cnt[1], 1);
    if (w > 1u)                               atomicAdd(&cnt[2], 1);
    __syncthreads();
    if (t == 0) {
        int mode;
        if (cnt[0] >= 4)      mode = 3;
        else if (cnt[1] >= 4) mode = 0;
        else if (cnt[2] > 0)  mode = 2;
        else                  mode = 1;
        g_maskmode = mode;
    }
}

__device__ __forceinline__ float mask_at(const void* M, int tok, int mode) {
    switch (mode) {
        case 0:  return ((const float*)M)[tok] != 0.0f ? 1.0f : 0.0f;
        case 1:  return ((const int*)M)[tok]   != 0    ? 1.0f : 0.0f;
        case 2:  return ((const unsigned char*)M)[tok] ? 1.0f : 0.0f;
        default: return ((const unsigned short*)M)[tok] ? 1.0f : 0.0f;
    }
}

// ---------------- grouping --------------------------------------------------------
__global__ void k_group2(const float* __restrict__ P, const float* __restrict__ Dr,
                         const void* __restrict__ MP, const void* __restrict__ MD) {
    int b = blockIdx.x;
    const float* X; const void* M; float* out; float* mout;
    if (b < NB*GP) { X = P;  M = MP; out = g_pg; mout = g_mp; }
    else           { b -= NB*GP; X = Dr; M = MD; out = g_dg; mout = g_md; }
    int d = threadIdx.x;
    const float* src = X + (size_t)b * 4 * DM;
    out[(size_t)b * DM + d] =
        0.25f * (src[d] + src[DM + d] + src[2*DM + d] + src[3*DM + d]);
    if (d == 0) {
        int mode = g_maskmode;
        float m = mask_at(M, 4*b+0, mode) + mask_at(M, 4*b+1, mode)
                + mask_at(M, 4*b+2, mode) + mask_at(M, 4*b+3, mode);
        mout[b] = (m > 0.0f) ? 1.0f : 0.0f;
    }
}

// ---------------- fused launch 1: masked-sum partials + projection GEMM ----------
#define ASTR 137
__global__ __launch_bounds__(256) void k_fuse1(const float* __restrict__ Wkp,
                                               const float* __restrict__ Wqd) {
    if (blockIdx.x < 512) {
        int s = blockIdx.x;
        int n = s & 15, ent = (s >> 4) & 1, seg = s >> 5;
        int d = threadIdx.x;
        const float* X = ent ? g_dg : g_pg;
        const float* m = ent ? g_md : g_mp;
        int G = ent ? GD : GP;
        int chunk = G / SEG;
        int g0 = seg * chunk;
        float a0 = 0.f, a1 = 0.f, a2 = 0.f, a3 = 0.f;
        for (int g = g0; g < g0 + chunk; g += 4) {
            a0 += m[n*G+g+0] * X[((size_t)(n*G+g+0))*DM + d];
            a1 += m[n*G+g+1] * X[((size_t)(n*G+g+1))*DM + d];
            a2 += m[n*G+g+2] * X[((size_t)(n*G+g+2))*DM + d];
            a3 += m[n*G+g+3] * X[((size_t)(n*G+g+3))*DM + d];
        }
        g_part[((ent*NB + n)*SEG + seg)*DM + d] = (a0 + a1) + (a2 + a3);
        if (d == 0) {
            float c = 0.0f;
            for (int g = g0; g < g0 + chunk; g++) c += m[n*G + g];
            g_cpart[(ent*NB + n)*SEG + seg] = c;
        }
        return;
    }
    int pb = blockIdx.x - 512;
    int bx = pb & 63, by = (pb >> 6) & 1, bz = pb >> 7;
    const float* X; const float* W; float* OUT; int L;
    if (bz == 0) { X = g_pg; W = Wkp; OUT = g_kp; L = GP; }
    else         { if (bx >= 16) return;
                   X = g_dg; W = Wqd; OUT = g_qd; L = GD; }
    __shared__ uint32_t AsH[32*ASTR];
    __shared__ uint32_t BsH[32*ASTR];

    int tid = threadIdx.x;
    int lane = tid & 31, w = tid >> 5;
    int g = lane >> 2, tk = lane & 3;
    int wm = (w & 3) * 32, wn = (w >> 2) * 64;
    int m0 = bx * 128, o0 = by * 128;

    float c[2][8][4];
#pragma unroll
    for (int mi = 0; mi < 2; mi++)
#pragma unroll
        for (int ni = 0; ni < 8; ni++)
#pragma unroll
            for (int r = 0; r < 4; r++) c[mi][ni][r] = 0.0f;

    for (int k0 = 0; k0 < 256; k0 += 32) {
#pragma unroll
        for (int s = 0; s < 4; s++) {
            int f = tid + s*256;
            int row = f >> 3, c4 = f & 7;
            float4 va = *(const float4*)&X[(size_t)(m0+row)*256 + k0 + c4*4];
            AsH[(c4*4+0)*ASTR + row] = tf32cvt(va.x);
            AsH[(c4*4+1)*ASTR + row] = tf32cvt(va.y);
            AsH[(c4*4+2)*ASTR + row] = tf32cvt(va.z);
            AsH[(c4*4+3)*ASTR + row] = tf32cvt(va.w);
            float4 vb = *(const float4*)&W[(size_t)(o0+row)*256 + k0 + c4*4];
            BsH[(c4*4+0)*ASTR + row] = tf32cvt(vb.x);
            BsH[(c4*4+1)*ASTR + row] = tf32cvt(vb.y);
            BsH[(c4*4+2)*ASTR + row] = tf32cvt(vb.z);
            BsH[(c4*4+3)*ASTR + row] = tf32cvt(vb.w);
        }
        __syncthreads();
#pragma unroll
        for (int kh = 0; kh < 4; kh++) {
            int kb = kh*8;
            uint32_t aH[2][4];
#pragma unroll
            for (int mi = 0; mi < 2; mi++) {
                int rb = wm + mi*16 + g;
                aH[mi][0] = AsH[(kb+tk  )*ASTR + rb];
                aH[mi][1] = AsH[(kb+tk  )*ASTR + rb + 8];
                aH[mi][2] = AsH[(kb+tk+4)*ASTR + rb];
                aH[mi][3] = AsH[(kb+tk+4)*ASTR + rb + 8];
            }
            uint32_t bH[8][2];
#pragma unroll
            for (int ni = 0; ni < 8; ni++) {
                int nb = wn + ni*8 + g;
                bH[ni][0] = BsH[(kb+tk  )*ASTR + nb];
                bH[ni][1] = BsH[(kb+tk+4)*ASTR + nb];
            }
#pragma unroll
            for (int mi = 0; mi < 2; mi++)
#pragma unroll
                for (int ni = 0; ni < 8; ni++) {
                    float* cc = c[mi][ni];
                    mma_tf32(cc[0],cc[1],cc[2],cc[3],
                             aH[mi][0],aH[mi][1],aH[mi][2],aH[mi][3],
                             bH[ni][0],bH[ni][1]);
                }
        }
        __syncthreads();
    }

#pragma unroll
    for (int mi = 0; mi < 2; mi++)
#pragma unroll
        for (int ni = 0; ni < 8; ni++) {
            int o = o0 + wn + ni*8 + 2*tk;
            int h = o >> 5, dd = o & 31;
            int m = m0 + wm + mi*16 + g;
            int nb = m / L, gg = m % L;
            float* dst = &OUT[(((size_t)(nb*HN + h))*L + gg)*HDM + dd];
            *(float2*)dst = make_float2(c[mi][ni][0], c[mi][ni][1]);
            int m2 = m + 8;
            int nb2 = m2 / L, gg2 = m2 % L;
            float* dst2 = &OUT[(((size_t)(nb2*HN + h))*L + gg2)*HDM + dd];
            *(float2*)dst2 = make_float2(c[mi][ni][2], c[mi][ni][3]);
        }
}

// ---------------- mega kernel: logits (TF32 MMA) + 4x Sinkhorn, E in smem ---------
// blocks [0,128): one slice each, 512 threads; blocks [128,144): vembed.
__global__ __launch_bounds__(512) void k_mega(const float* __restrict__ Wvp,
                                              const float* __restrict__ Wvd,
                                              float* __restrict__ qout, int do_q) {
    extern __shared__ char smem[];
    int tid = threadIdx.x;
    int lane = tid & 31, w = tid >> 5;

    if (blockIdx.x >= NHS) {
        // ---- query embedding (all 512 threads participate in syncs) ----
        if (!do_q) return;
        float* sp   = (float*)smem;
        float* sd   = sp + DM;
        float* cnts = sd + DM;
        int n = blockIdx.x - NHS;
        if (tid < DM) {
            float accp = 0.0f, accd = 0.0f;
#pragma unroll
            for (int s = 0; s < SEG; s++) {
                accp += g_part[((0*NB + n)*SEG + s)*DM + tid];
                accd += g_part[((1*NB + n)*SEG + s)*DM + tid];
            }
            sp[tid] = accp; sd[tid] = accd;
        }
        if (tid < 2) {
            float c = 0.0f;
#pragma unroll
            for (int s = 0; s < SEG; s++) c += g_cpart[(tid*NB + n)*SEG + s];
            cnts[tid] = c;
        }
        __syncthreads();
        float cp = cnts[0], cd = cnts[1];
        for (int o = w; o < DM; o += 16) {
            float acc = 0.0f;
#pragma unroll
            for (int t = 0; t < 8; t++) {
                int k = lane + t*32;
                acc += sp[k]*Wvp[(size_t)o*DM + k] + sd[k]*Wvd[(size_t)o*DM + k];
            }
#pragma unroll
            for (int off = 16; off > 0; off >>= 1)
                acc += __shfl_xor_sync(0xFFFFFFFFu, acc, off);
            if (lane == 0) {
                qout[(size_t)n*512 + o]       = 0.5f * acc / cp;
                qout[(size_t)n*512 + 256 + o] = 0.5f * acc / cd;
            }
        }
        return;
    }

    // ---- per-slice logits + Sinkhorn ----
    int slice = blockIdx.x;
    int n = slice >> 3;
    const float* q = g_qd + (size_t)slice * GD * HDM;
    const float* k = g_kp + (size_t)slice * GP * HDM;

    __half*   Esm   = (__half*)(smem + SM_E);
    uint32_t* Qs    = (uint32_t*)(smem + SM_QK);
    uint32_t* Ks    = Qs + 32*ASTR;
    float*    strip = (float*)(smem + SM_QK);      // aliases Qs/Ks after compute
    float*    mr    = (float*)(smem + SM_MR);
    float*    mc    = (float*)(smem + SM_MC);

    int g = lane >> 2, tk = lane & 3;
    int wm = (w & 3) * 32, wn = (w >> 2) * 32;     // 16 warps: 4(M) x 4(N), warp 32x32

    // fill Q (128x32) once: 1024 float4, 2 per thread
#pragma unroll
    for (int s = 0; s < 2; s++) {
        int f = tid + s*512;
        int row = f >> 3, c4 = f & 7;
        float4 v = *(const float4*)&q[(size_t)row*HDM + c4*4];
        Qs[(c4*4+0)*ASTR + row] = tf32cvt(v.x);
        Qs[(c4*4+1)*ASTR + row] = tf32cvt(v.y);
        Qs[(c4*4+2)*ASTR + row] = tf32cvt(v.z);
        Qs[(c4*4+3)*ASTR + row] = tf32cvt(v.w);
    }
    if (tid < 128) mr[tid] = g_md[n*GD + tid];
    mc[tid] = g_mp[n*GP + tid];

    for (int jt = 0; jt < 4; jt++) {
        int j0 = jt * 128;
        // fill K tile (128x32): 1024 float4, 2 per thread
#pragma unroll
        for (int s = 0; s < 2; s++) {
            int f = tid + s*512;
            int row = f >> 3, c4 = f & 7;
            float4 v = *(const float4*)&k[(size_t)(j0+row)*HDM + c4*4];
            Ks[(c4*4+0)*ASTR + row] = tf32cvt(v.x);
            Ks[(c4*4+1)*ASTR + row] = tf32cvt(v.y);
            Ks[(c4*4+2)*ASTR + row] = tf32cvt(v.z);
            Ks[(c4*4+3)*ASTR + row] = tf32cvt(v.w);
        }
        __syncthreads();

        float c[2][4][4];
#pragma unroll
        for (int mi = 0; mi < 2; mi++)
#pragma unroll
            for (int ni = 0; ni < 4; ni++)
#pragma unroll
                for (int r = 0; r < 4; r++) c[mi][ni][r] = 0.0f;

#pragma unroll
        for (int kh = 0; kh < 4; kh++) {
            int kb = kh*8;
            uint32_t aH[2][4];
#pragma unroll
            for (int mi = 0; mi < 2; mi++) {
                int rb = wm + mi*16 + g;
                aH[mi][0] = Qs[(kb+tk  )*ASTR + rb];
                aH[mi][1] = Qs[(kb+tk  )*ASTR + rb + 8];
                aH[mi][2] = Qs[(kb+tk+4)*ASTR + rb];
                aH[mi][3] = Qs[(kb+tk+4)*ASTR + rb + 8];
            }
            uint32_t bH[4][2];
#pragma unroll
            for (int ni = 0; ni < 4; ni++) {
                int nb = wn + ni*8 + g;
                bH[ni][0] = Ks[(kb+tk  )*ASTR + nb];
                bH[ni][1] = Ks[(kb+tk+4)*ASTR + nb];
            }
#pragma unroll
            for (int mi = 0; mi < 2; mi++)
#pragma unroll
                for (int ni = 0; ni < 4; ni++) {
                    float* cc = c[mi][ni];
                    mma_tf32(cc[0],cc[1],cc[2],cc[3],
                             aH[mi][0],aH[mi][1],aH[mi][2],aH[mi][3],
                             bH[ni][0],bH[ni][1]);
                }
        }

        // epilogue: mask + ex2.f16x2, write into Esm (conflict-free: bank=4row+tk+c)
#pragma unroll
        for (int mi = 0; mi < 2; mi++) {
            int row1 = wm + mi*16 + g;
            int row2 = row1 + 8;
            float rm1 = mr[row1], rm2 = mr[row2];
#pragma unroll
            for (int ni = 0; ni < 4; ni++) {
                int o  = wn + ni*8 + 2*tk;
                int oc = j0 + o;
                float m0v = mc[oc], m1v = mc[oc+1];
                float* cc = c[mi][ni];
                __half2 xa = __floats2half2_rn(cc[0]*EXPSC, cc[1]*EXPSC);
                uint32_t ea = ex2_f16x2(*(uint32_t*)&xa);
                __half2 ma = __floats2half2_rn(rm1*m0v, rm1*m1v);
                *(__half2*)&Esm[row1*ESTR + oc] = __hmul2(*(__half2*)&ea, ma);
                __half2 xb = __floats2half2_rn(cc[2]*EXPSC, cc[3]*EXPSC);
                uint32_t eb = ex2_f16x2(*(uint32_t*)&xb);
                __half2 mb = __floats2half2_rn(rm2*m0v, rm2*m1v);
                *(__half2*)&Esm[row2*ESTR + oc] = __hmul2(*(__half2*)&eb, mb);
            }
        }
        __syncthreads();     // protect Ks before next tile / strips after last
    }

    // ---- 4 Sinkhorn iterations out of smem (strips alias Qs/Ks region) ----
    float cv[16];
#pragma unroll
    for (int u = 0; u < 16; u++) cv[u] = 1.0f;

    for (int iter = 0; iter < 4; iter++) {
        float colacc[16];
#pragma unroll
        for (int u = 0; u < 16; u++) colacc[u] = 0.0f;

#pragma unroll
        for (int ridx = 0; ridx < 8; ridx++) {
            int i = w + ridx*16;
            const uint4* rp = (const uint4*)(Esm + (size_t)i * ESTR);
            float ev[16];
            float s = 0.0f;
            uint4 raws[2];
#pragma unroll
            for (int ch = 0; ch < 2; ch++) {
                uint4 raw = rp[ch*32 + lane];
                raws[ch] = raw;
                float2 f0 = __half22float2(*(__half2*)&raw.x);
                float2 f1 = __half22float2(*(__half2*)&raw.y);
                float2 f2 = __half22float2(*(__half2*)&raw.z);
                float2 f3 = __half22float2(*(__half2*)&raw.w);
                ev[ch*8+0] = f0.x; ev[ch*8+1] = f0.y;
                ev[ch*8+2] = f1.x; ev[ch*8+3] = f1.y;
                ev[ch*8+4] = f2.x; ev[ch*8+5] = f2.y;
                ev[ch*8+6] = f3.x; ev[ch*8+7] = f3.y;
            }
#pragma unroll
            for (int u = 0; u < 16; u++) s += ev[u] * cv[u];
#pragma unroll
            for (int off = 16; off > 0; off >>= 1)
                s += __shfl_xor_sync(0xFFFFFFFFu, s, off);
            float r = (s > 0.0f) ? 1.0f/s : 0.0f;
            if (iter == 3) {
                if (lane == 0) g_r[slice*GD + i] = r;
                // coalesced global E writeback for k_adp
                uint4* gp = (uint4*)(g_E + (size_t)slice*GD*GP + (size_t)i*GP);
                gp[lane]      = raws[0];
                gp[32 + lane] = raws[1];
            }
#pragma unroll
            for (int u = 0; u < 16; u++) colacc[u] += r * ev[u];
        }
#pragma unroll
        for (int u = 0; u < 16; u++) {
            int cc = (u >> 3)*256 + lane*8 + (u & 7);
            strip[w*544 + SIDX(cc)] = colacc[u];
        }
        __syncthreads();
        {
            int cc = tid;
            float s2 = 0.0f;
#pragma unroll
            for (int ww = 0; ww < 16; ww++) s2 += strip[ww*544 + SIDX(cc)];
            float rec = (s2 > 0.0f) ? 1.0f/s2 : 0.0f;
            if (iter == 3) g_c[slice*GP + cc] = rec;
            else           strip[SIDX(cc)] = rec;
        }
        __syncthreads();
        if (iter < 3) {
#pragma unroll
            for (int u = 0; u < 16; u++) {
                int cc = (u >> 3)*256 + lane*8 + (u & 7);
                cv[u] = strip[SIDX(cc)];
            }
            __syncthreads();
        }
    }
}

// ---------------- write a_dp = diag(r) E diag(c) in [n,i,j,h] layout --------------
__global__ __launch_bounds__(256) void k_adp(float* __restrict__ out) {
    __shared__ __half shE[8][512];
    __shared__ float  csh[8][512];
    __shared__ float  rsh[8];
    int b = blockIdx.x;
    int n = b >> 7, i = b & 127;
    int tid = threadIdx.x;

    if (tid < 8) rsh[tid] = g_r[(n*8 + tid)*GD + i];
#pragma unroll
    for (int t = 0; t < 2; t++) {
        int f = t*256 + tid;
        int h = f >> 6, qq = f & 63;
        ((uint4*)&shE[h][0])[qq] =
            ((const uint4*)(g_E + ((size_t)(n*8 + h)*GD + i)*GP))[qq];
    }
#pragma unroll
    for (int t = 0; t < 4; t++) {
        int f = t*256 + tid;
        int h = f >> 7, j4 = f & 127;
        ((float4*)&csh[h][0])[j4] =
            ((const float4*)(g_c + (size_t)(n*8 + h)*GP))[j4];
    }
    __syncthreads();

    float* dst = out + (size_t)b * GP * 8;
#pragma unroll
    for (int t = 0; t < 16; t++) {
        int o = t*256 + tid;
        int j = o >> 3, h = o & 7;
        float e = __half2float(shE[h][j]);
        dst[o] = rsh[h] * e * csh[h][j];
    }
}

// ---------------- launch -----------------------------------------------------------
extern "C" void kernel_launch(void* const* d_in, const int* in_sizes, int n_in,
                              void* d_out, int out_size) {
    const float* protein = (const float*)d_in[0];
    const float* drug    = (const float*)d_in[1];
    const void*  maskp   = d_in[2];
    const void*  maskd   = d_in[3];
    const float* Wk_p    = (const float*)d_in[5];
    const float* Wv_p    = (const float*)d_in[6];
    const float* Wq_d    = (const float*)d_in[7];
    const float* Wv_d    = (const float*)d_in[9];
    float* out = (float*)d_out;

    size_t adp_elems = (size_t)NB * GD * GP * HN;
    int  write_q   = (((size_t)out_size > adp_elems) || ((size_t)out_size < adp_elems)) ? 1 : 0;
    bool write_adp = ((size_t)out_size >= adp_elems);
    size_t adp_off = ((size_t)out_size >= adp_elems + NB*512) ? (size_t)NB*512 : 0;

    static int smem_set = 0;
    if (!smem_set) {
        cudaFuncSetAttribute(k_mega, cudaFuncAttributeMaxDynamicSharedMemorySize, SM_TOT);
        smem_set = 1;
    }

    k_probe<<<1, 256>>>((const unsigned int*)maskp);
    k_group2<<<NB*GP + NB*GD, 256>>>(protein, drug, maskp, maskd);
    k_fuse1<<<768, 256>>>(Wk_p, Wq_d);
    k_mega<<<NHS + NB, 512, SM_TOT>>>(Wv_p, Wv_d, out, write_q);
    if (write_adp) {
        k_adp<<<NB*GD, 256>>>(out + adp_off);
    }
}